// round 1
// baseline (speedup 1.0000x reference)
#include <cuda_runtime.h>
#include <cuda_bf16.h>
#include <stdint.h>

// Problem dims (fixed)
#define B_ 2
#define D_ 4096
#define S_ 2048
#define F_ 16384

// ---------------------------------------------------------------------------
// Scratch (device globals; allocation-free per harness rules)
// ---------------------------------------------------------------------------
__device__ __nv_bfloat16 g_xhi[(size_t)B_ * D_ * S_];
__device__ __nv_bfloat16 g_xlo[(size_t)B_ * D_ * S_];
__device__ __nv_bfloat16 g_w0hi[(size_t)F_ * D_];
__device__ __nv_bfloat16 g_w0lo[(size_t)F_ * D_];
__device__ __nv_bfloat16 g_w1hi[(size_t)F_ * D_];
__device__ __nv_bfloat16 g_w1lo[(size_t)F_ * D_];
__device__ __nv_bfloat16 g_wohi[(size_t)D_ * F_];
__device__ __nv_bfloat16 g_wolo[(size_t)D_ * F_];
__device__ float         g_y0[(size_t)B_ * F_ * S_];
__device__ float         g_y1[(size_t)B_ * F_ * S_];
__device__ __nv_bfloat16 g_hhi[(size_t)B_ * F_ * S_];
__device__ __nv_bfloat16 g_hlo[(size_t)B_ * F_ * S_];

// ---------------------------------------------------------------------------
// Elementwise kernels
// ---------------------------------------------------------------------------
__global__ void split_kernel(const float4* __restrict__ in,
                             ushort4* __restrict__ hi,
                             ushort4* __restrict__ lo, int n4) {
    int i = blockIdx.x * blockDim.x + threadIdx.x;
    if (i >= n4) return;
    float4 v = in[i];
    __nv_bfloat16 h0 = __float2bfloat16(v.x);
    __nv_bfloat16 h1 = __float2bfloat16(v.y);
    __nv_bfloat16 h2 = __float2bfloat16(v.z);
    __nv_bfloat16 h3 = __float2bfloat16(v.w);
    ushort4 H;
    H.x = __bfloat16_as_ushort(h0);
    H.y = __bfloat16_as_ushort(h1);
    H.z = __bfloat16_as_ushort(h2);
    H.w = __bfloat16_as_ushort(h3);
    hi[i] = H;
    ushort4 L;
    L.x = __bfloat16_as_ushort(__float2bfloat16(v.x - __bfloat162float(h0)));
    L.y = __bfloat16_as_ushort(__float2bfloat16(v.y - __bfloat162float(h1)));
    L.z = __bfloat16_as_ushort(__float2bfloat16(v.z - __bfloat162float(h2)));
    L.w = __bfloat16_as_ushort(__float2bfloat16(v.w - __bfloat162float(h3)));
    lo[i] = L;
}

__device__ __forceinline__ float gelu_exact(float v) {
    return 0.5f * v * (1.0f + erff(v * 0.70710678118654752440f));
}

__global__ void h_kernel(const float4* __restrict__ y0,
                         const float4* __restrict__ y1,
                         ushort4* __restrict__ hhi,
                         ushort4* __restrict__ hlo, int n4) {
    int i = blockIdx.x * blockDim.x + threadIdx.x;
    if (i >= n4) return;
    float4 a = y0[i];
    float4 b = y1[i];
    float v0 = gelu_exact(a.x) * b.x;
    float v1 = gelu_exact(a.y) * b.y;
    float v2 = gelu_exact(a.z) * b.z;
    float v3 = gelu_exact(a.w) * b.w;
    __nv_bfloat16 h0 = __float2bfloat16(v0);
    __nv_bfloat16 h1 = __float2bfloat16(v1);
    __nv_bfloat16 h2 = __float2bfloat16(v2);
    __nv_bfloat16 h3 = __float2bfloat16(v3);
    ushort4 H;
    H.x = __bfloat16_as_ushort(h0);
    H.y = __bfloat16_as_ushort(h1);
    H.z = __bfloat16_as_ushort(h2);
    H.w = __bfloat16_as_ushort(h3);
    hhi[i] = H;
    ushort4 L;
    L.x = __bfloat16_as_ushort(__float2bfloat16(v0 - __bfloat162float(h0)));
    L.y = __bfloat16_as_ushort(__float2bfloat16(v1 - __bfloat162float(h1)));
    L.z = __bfloat16_as_ushort(__float2bfloat16(v2 - __bfloat162float(h2)));
    L.w = __bfloat16_as_ushort(__float2bfloat16(v3 - __bfloat162float(h3)));
    hlo[i] = L;
}

// ---------------------------------------------------------------------------
// bf16x3 GEMM:  C[M,N] (fp32) = (Ahi+Alo)[M,K] @ (Bhi+Blo)[K,N]
//               computed as Ahi*Bhi + Ahi*Blo + Alo*Bhi  (fp32 accum)
// A row-major MxK, B row-major KxN. M,N,K multiples of 128/128/32.
// Block tile 128x128x32, 256 threads (8 warps, 4x2), warp tile 32x64.
// Double-buffered cp.async; padded smem for conflict-free ldmatrix.
// ---------------------------------------------------------------------------
constexpr int BM = 128, BN = 128, BK = 32;
constexpr int LDA_S = 40;    // A smem row stride (elems): conflict-free ldmatrix
constexpr int LDB_S = 136;   // B smem row stride (elems): conflict-free ldmatrix.trans
constexpr int A_TILE = BM * LDA_S * 2;   // 10240 B
constexpr int B_TILE = BK * LDB_S * 2;   // 8704 B
constexpr int BUF = 2 * A_TILE + 2 * B_TILE;  // 37888 B (Ahi,Alo,Bhi,Blo)
constexpr int SMEM_BYTES = 2 * BUF;           // 75776 B double-buffered

__device__ __forceinline__ void cp16(uint32_t s, const void* g) {
    asm volatile("cp.async.cg.shared.global [%0], [%1], 16;\n" :: "r"(s), "l"(g));
}

__device__ __forceinline__ void load_tiles(
    uint32_t sbuf,
    const __nv_bfloat16* __restrict__ Ahi, const __nv_bfloat16* __restrict__ Alo,
    const __nv_bfloat16* __restrict__ Bhi, const __nv_bfloat16* __restrict__ Blo,
    int m0, int n0, int k0, int N, int K, int tid) {
    uint32_t sAhi = sbuf;
    uint32_t sAlo = sbuf + A_TILE;
    uint32_t sBhi = sbuf + 2 * A_TILE;
    uint32_t sBlo = sbuf + 2 * A_TILE + B_TILE;
    // A: 128 rows x 32 cols, 16B chunks: 512 chunks
    #pragma unroll
    for (int t = tid; t < 512; t += 256) {
        int row = t >> 2, c8 = (t & 3) * 8;
        size_t g = (size_t)(m0 + row) * K + k0 + c8;
        uint32_t s = (uint32_t)(row * LDA_S + c8) * 2;
        cp16(sAhi + s, Ahi + g);
        cp16(sAlo + s, Alo + g);
    }
    // B: 32 rows x 128 cols, 16B chunks: 512 chunks
    #pragma unroll
    for (int t = tid; t < 512; t += 256) {
        int row = t >> 4, c8 = (t & 15) * 8;
        size_t g = (size_t)(k0 + row) * N + n0 + c8;
        uint32_t s = (uint32_t)(row * LDB_S + c8) * 2;
        cp16(sBhi + s, Bhi + g);
        cp16(sBlo + s, Blo + g);
    }
}

__global__ void __launch_bounds__(256, 1) gemm_bf16x3(
    const __nv_bfloat16* __restrict__ Ahi, const __nv_bfloat16* __restrict__ Alo,
    const __nv_bfloat16* __restrict__ Bhi, const __nv_bfloat16* __restrict__ Blo,
    float* __restrict__ C, int N, int K) {
    extern __shared__ char smem[];
    uint32_t sbase = (uint32_t)__cvta_generic_to_shared(smem);
    int tid = threadIdx.x;
    int lane = tid & 31, wid = tid >> 5;
    int wm = wid & 3;        // 4 warps along M
    int wn = wid >> 2;       // 2 warps along N
    int m0 = blockIdx.y * BM;
    int n0 = blockIdx.x * BN;

    float c[2][8][4];
    #pragma unroll
    for (int mi = 0; mi < 2; ++mi)
        #pragma unroll
        for (int ni = 0; ni < 8; ++ni)
            #pragma unroll
            for (int r = 0; r < 4; ++r) c[mi][ni][r] = 0.0f;

    int KT = K / BK;
    load_tiles(sbase, Ahi, Alo, Bhi, Blo, m0, n0, 0, N, K, tid);
    asm volatile("cp.async.commit_group;\n" ::: "memory");

    for (int kt = 0; kt < KT; ++kt) {
        int buf = kt & 1;
        __syncthreads();  // buffer (buf^1) free to overwrite
        if (kt + 1 < KT) {
            load_tiles(sbase + (buf ^ 1) * BUF, Ahi, Alo, Bhi, Blo,
                       m0, n0, (kt + 1) * BK, N, K, tid);
            asm volatile("cp.async.commit_group;\n" ::: "memory");
            asm volatile("cp.async.wait_group 1;\n" ::: "memory");
        } else {
            asm volatile("cp.async.wait_group 0;\n" ::: "memory");
        }
        __syncthreads();

        uint32_t sb = sbase + buf * BUF;
        uint32_t aS[2] = { sb, sb + A_TILE };                      // hi, lo
        uint32_t bS[2] = { sb + 2 * A_TILE, sb + 2 * A_TILE + B_TILE };

        #pragma unroll
        for (int p = 0; p < 3; ++p) {
            // p0: Ahi*Bhi, p1: Ahi*Blo, p2: Alo*Bhi
            uint32_t a_s = aS[p == 2 ? 1 : 0];
            uint32_t b_s = bS[p == 1 ? 1 : 0];
            #pragma unroll
            for (int ks = 0; ks < 2; ++ks) {
                uint32_t ar[2][4];
                #pragma unroll
                for (int mi = 0; mi < 2; ++mi) {
                    int row = wm * 32 + mi * 16 + (lane & 15);
                    int col = ks * 16 + (lane >> 4) * 8;
                    uint32_t addr = a_s + (uint32_t)(row * LDA_S + col) * 2;
                    asm volatile(
                        "ldmatrix.sync.aligned.m8n8.x4.shared.b16 {%0,%1,%2,%3}, [%4];\n"
                        : "=r"(ar[mi][0]), "=r"(ar[mi][1]), "=r"(ar[mi][2]), "=r"(ar[mi][3])
                        : "r"(addr));
                }
                uint32_t br[8][2];
                #pragma unroll
                for (int nj = 0; nj < 4; ++nj) {
                    int row = ks * 16 + (lane & 15);
                    int col = wn * 64 + nj * 16 + (lane >> 4) * 8;
                    uint32_t addr = b_s + (uint32_t)(row * LDB_S + col) * 2;
                    asm volatile(
                        "ldmatrix.sync.aligned.m8n8.x4.trans.shared.b16 {%0,%1,%2,%3}, [%4];\n"
                        : "=r"(br[2 * nj][0]), "=r"(br[2 * nj][1]),
                          "=r"(br[2 * nj + 1][0]), "=r"(br[2 * nj + 1][1])
                        : "r"(addr));
                }
                #pragma unroll
                for (int mi = 0; mi < 2; ++mi)
                    #pragma unroll
                    for (int ni = 0; ni < 8; ++ni)
                        asm volatile(
                            "mma.sync.aligned.m16n8k16.row.col.f32.bf16.bf16.f32 "
                            "{%0,%1,%2,%3}, {%4,%5,%6,%7}, {%8,%9}, {%0,%1,%2,%3};\n"
                            : "+f"(c[mi][ni][0]), "+f"(c[mi][ni][1]),
                              "+f"(c[mi][ni][2]), "+f"(c[mi][ni][3])
                            : "r"(ar[mi][0]), "r"(ar[mi][1]), "r"(ar[mi][2]), "r"(ar[mi][3]),
                              "r"(br[ni][0]), "r"(br[ni][1]));
            }
        }
    }

    // Epilogue: c frags -> C (fp32, row-major, ld = N)
    #pragma unroll
    for (int mi = 0; mi < 2; ++mi) {
        #pragma unroll
        for (int ni = 0; ni < 8; ++ni) {
            int row = m0 + wm * 32 + mi * 16 + (lane >> 2);
            int col = n0 + wn * 64 + ni * 8 + (lane & 3) * 2;
            float* o = C + (size_t)row * N + col;
            o[0] = c[mi][ni][0];
            o[1] = c[mi][ni][1];
            o[(size_t)8 * N]     = c[mi][ni][2];
            o[(size_t)8 * N + 1] = c[mi][ni][3];
        }
    }
}

// ---------------------------------------------------------------------------
// Launch
// ---------------------------------------------------------------------------
extern "C" void kernel_launch(void* const* d_in, const int* in_sizes, int n_in,
                              void* d_out, int out_size) {
    const float* x    = (const float*)d_in[0];
    const float* w0   = (const float*)d_in[1];
    const float* w1   = (const float*)d_in[2];
    const float* wout = (const float*)d_in[3];
    float* out = (float*)d_out;

    void *xhi, *xlo, *w0hi, *w0lo, *w1hi, *w1lo, *wohi, *wolo, *y0, *y1, *hhi, *hlo;
    cudaGetSymbolAddress(&xhi,  g_xhi);
    cudaGetSymbolAddress(&xlo,  g_xlo);
    cudaGetSymbolAddress(&w0hi, g_w0hi);
    cudaGetSymbolAddress(&w0lo, g_w0lo);
    cudaGetSymbolAddress(&w1hi, g_w1hi);
    cudaGetSymbolAddress(&w1lo, g_w1lo);
    cudaGetSymbolAddress(&wohi, g_wohi);
    cudaGetSymbolAddress(&wolo, g_wolo);
    cudaGetSymbolAddress(&y0,   g_y0);
    cudaGetSymbolAddress(&y1,   g_y1);
    cudaGetSymbolAddress(&hhi,  g_hhi);
    cudaGetSymbolAddress(&hlo,  g_hlo);

    cudaFuncSetAttribute(gemm_bf16x3,
                         cudaFuncAttributeMaxDynamicSharedMemorySize, SMEM_BYTES);

    const int nX = B_ * D_ * S_;   // 16,777,216
    const int nW = F_ * D_;        // 67,108,864
    const int nH = B_ * F_ * S_;   // 67,108,864

    // 1) split inputs into bf16 hi/lo
    split_kernel<<<nX / 4 / 256, 256>>>((const float4*)x,    (ushort4*)xhi,  (ushort4*)xlo,  nX / 4);
    split_kernel<<<nW / 4 / 256, 256>>>((const float4*)w0,   (ushort4*)w0hi, (ushort4*)w0lo, nW / 4);
    split_kernel<<<nW / 4 / 256, 256>>>((const float4*)w1,   (ushort4*)w1hi, (ushort4*)w1lo, nW / 4);
    split_kernel<<<nW / 4 / 256, 256>>>((const float4*)wout, (ushort4*)wohi, (ushort4*)wolo, nW / 4);

    // 2) layer 1: Y0 = w0 @ x_b, Y1 = w1 @ x_b  (per batch)
    dim3 g1(S_ / BN, F_ / BM);  // (16, 128)
    for (int b = 0; b < B_; ++b) {
        const __nv_bfloat16* bx_hi = (const __nv_bfloat16*)xhi + (size_t)b * D_ * S_;
        const __nv_bfloat16* bx_lo = (const __nv_bfloat16*)xlo + (size_t)b * D_ * S_;
        gemm_bf16x3<<<g1, 256, SMEM_BYTES>>>(
            (const __nv_bfloat16*)w0hi, (const __nv_bfloat16*)w0lo,
            bx_hi, bx_lo,
            (float*)y0 + (size_t)b * F_ * S_, S_, D_);
        gemm_bf16x3<<<g1, 256, SMEM_BYTES>>>(
            (const __nv_bfloat16*)w1hi, (const __nv_bfloat16*)w1lo,
            bx_hi, bx_lo,
            (float*)y1 + (size_t)b * F_ * S_, S_, D_);
    }

    // 3) H = gelu(Y0) * Y1, split to bf16 hi/lo
    h_kernel<<<nH / 4 / 256, 256>>>((const float4*)y0, (const float4*)y1,
                                    (ushort4*)hhi, (ushort4*)hlo, nH / 4);

    // 4) layer 2: out_b = w_out @ H_b
    dim3 g2(S_ / BN, D_ / BM);  // (16, 32)
    for (int b = 0; b < B_; ++b) {
        gemm_bf16x3<<<g2, 256, SMEM_BYTES>>>(
            (const __nv_bfloat16*)wohi, (const __nv_bfloat16*)wolo,
            (const __nv_bfloat16*)hhi + (size_t)b * F_ * S_,
            (const __nv_bfloat16*)hlo + (size_t)b * F_ * S_,
            out + (size_t)b * D_ * S_, S_, F_);
    }
}

// round 2
// speedup vs baseline: 1.5444x; 1.5444x over previous
#include <cuda_runtime.h>
#include <cuda_bf16.h>
#include <stdint.h>

// Problem dims (fixed)
#define B_ 2
#define D_ 4096
#define S_ 2048
#define F_ 16384

// ---------------------------------------------------------------------------
// Scratch (device globals; allocation-free per harness rules)
// ---------------------------------------------------------------------------
__device__ __nv_bfloat16 g_xhi[(size_t)B_ * D_ * S_];
__device__ __nv_bfloat16 g_xlo[(size_t)B_ * D_ * S_];
__device__ __nv_bfloat16 g_w0hi[(size_t)F_ * D_];
__device__ __nv_bfloat16 g_w0lo[(size_t)F_ * D_];
__device__ __nv_bfloat16 g_w1hi[(size_t)F_ * D_];
__device__ __nv_bfloat16 g_w1lo[(size_t)F_ * D_];
__device__ __nv_bfloat16 g_wohi[(size_t)D_ * F_];
__device__ __nv_bfloat16 g_wolo[(size_t)D_ * F_];
__device__ float         g_y0[(size_t)B_ * F_ * S_];
__device__ float         g_y1[(size_t)B_ * F_ * S_];
__device__ __nv_bfloat16 g_hhi[(size_t)B_ * F_ * S_];
__device__ __nv_bfloat16 g_hlo[(size_t)B_ * F_ * S_];

// ---------------------------------------------------------------------------
// Elementwise kernels
// ---------------------------------------------------------------------------
__global__ void split_kernel(const float4* __restrict__ in,
                             ushort4* __restrict__ hi,
                             ushort4* __restrict__ lo, int n4) {
    int i = blockIdx.x * blockDim.x + threadIdx.x;
    if (i >= n4) return;
    float4 v = in[i];
    __nv_bfloat16 h0 = __float2bfloat16(v.x);
    __nv_bfloat16 h1 = __float2bfloat16(v.y);
    __nv_bfloat16 h2 = __float2bfloat16(v.z);
    __nv_bfloat16 h3 = __float2bfloat16(v.w);
    ushort4 H;
    H.x = __bfloat16_as_ushort(h0);
    H.y = __bfloat16_as_ushort(h1);
    H.z = __bfloat16_as_ushort(h2);
    H.w = __bfloat16_as_ushort(h3);
    hi[i] = H;
    ushort4 L;
    L.x = __bfloat16_as_ushort(__float2bfloat16(v.x - __bfloat162float(h0)));
    L.y = __bfloat16_as_ushort(__float2bfloat16(v.y - __bfloat162float(h1)));
    L.z = __bfloat16_as_ushort(__float2bfloat16(v.z - __bfloat162float(h2)));
    L.w = __bfloat16_as_ushort(__float2bfloat16(v.w - __bfloat162float(h3)));
    lo[i] = L;
}

__device__ __forceinline__ float gelu_exact(float v) {
    return 0.5f * v * (1.0f + erff(v * 0.70710678118654752440f));
}

__global__ void h_kernel(const float4* __restrict__ y0,
                         const float4* __restrict__ y1,
                         ushort4* __restrict__ hhi,
                         ushort4* __restrict__ hlo, int n4) {
    int i = blockIdx.x * blockDim.x + threadIdx.x;
    if (i >= n4) return;
    float4 a = y0[i];
    float4 b = y1[i];
    float v0 = gelu_exact(a.x) * b.x;
    float v1 = gelu_exact(a.y) * b.y;
    float v2 = gelu_exact(a.z) * b.z;
    float v3 = gelu_exact(a.w) * b.w;
    __nv_bfloat16 h0 = __float2bfloat16(v0);
    __nv_bfloat16 h1 = __float2bfloat16(v1);
    __nv_bfloat16 h2 = __float2bfloat16(v2);
    __nv_bfloat16 h3 = __float2bfloat16(v3);
    ushort4 H;
    H.x = __bfloat16_as_ushort(h0);
    H.y = __bfloat16_as_ushort(h1);
    H.z = __bfloat16_as_ushort(h2);
    H.w = __bfloat16_as_ushort(h3);
    hhi[i] = H;
    ushort4 L;
    L.x = __bfloat16_as_ushort(__float2bfloat16(v0 - __bfloat162float(h0)));
    L.y = __bfloat16_as_ushort(__float2bfloat16(v1 - __bfloat162float(h1)));
    L.z = __bfloat16_as_ushort(__float2bfloat16(v2 - __bfloat162float(h2)));
    L.w = __bfloat16_as_ushort(__float2bfloat16(v3 - __bfloat162float(h3)));
    hlo[i] = L;
}

// ---------------------------------------------------------------------------
// bf16x3 GEMM:  C[M,N] (fp32) = (Ahi+Alo)[M,K] @ (Bhi+Blo)[K,N]
//               computed as Ahi*Bhi + Ahi*Blo + Alo*Bhi  (fp32 accum)
// A row-major MxK, B row-major KxN. M,N,K multiples of 128/128/32.
// Block tile 128x128x32, 256 threads (8 warps, 4x2), warp tile 32x64.
// Double-buffered cp.async; padded smem for conflict-free ldmatrix.
// ---------------------------------------------------------------------------
constexpr int BM = 128, BN = 128, BK = 32;
constexpr int LDA_S = 40;    // A smem row stride (elems): conflict-free ldmatrix
constexpr int LDB_S = 136;   // B smem row stride (elems): conflict-free ldmatrix.trans
constexpr int A_TILE = BM * LDA_S * 2;   // 10240 B
constexpr int B_TILE = BK * LDB_S * 2;   // 8704 B
constexpr int BUF = 2 * A_TILE + 2 * B_TILE;  // 37888 B (Ahi,Alo,Bhi,Blo)
constexpr int SMEM_BYTES = 2 * BUF;           // 75776 B double-buffered

__device__ __forceinline__ void cp16(uint32_t s, const void* g) {
    asm volatile("cp.async.cg.shared.global [%0], [%1], 16;\n" :: "r"(s), "l"(g));
}

__device__ __forceinline__ void load_tiles(
    uint32_t sbuf,
    const __nv_bfloat16* __restrict__ Ahi, const __nv_bfloat16* __restrict__ Alo,
    const __nv_bfloat16* __restrict__ Bhi, const __nv_bfloat16* __restrict__ Blo,
    int m0, int n0, int k0, int N, int K, int tid) {
    uint32_t sAhi = sbuf;
    uint32_t sAlo = sbuf + A_TILE;
    uint32_t sBhi = sbuf + 2 * A_TILE;
    uint32_t sBlo = sbuf + 2 * A_TILE + B_TILE;
    // A: 128 rows x 32 cols, 16B chunks: 512 chunks
    #pragma unroll
    for (int t = tid; t < 512; t += 256) {
        int row = t >> 2, c8 = (t & 3) * 8;
        size_t g = (size_t)(m0 + row) * K + k0 + c8;
        uint32_t s = (uint32_t)(row * LDA_S + c8) * 2;
        cp16(sAhi + s, Ahi + g);
        cp16(sAlo + s, Alo + g);
    }
    // B: 32 rows x 128 cols, 16B chunks: 512 chunks
    #pragma unroll
    for (int t = tid; t < 512; t += 256) {
        int row = t >> 4, c8 = (t & 15) * 8;
        size_t g = (size_t)(k0 + row) * N + n0 + c8;
        uint32_t s = (uint32_t)(row * LDB_S + c8) * 2;
        cp16(sBhi + s, Bhi + g);
        cp16(sBlo + s, Blo + g);
    }
}

__global__ void __launch_bounds__(256, 1) gemm_bf16x3(
    const __nv_bfloat16* __restrict__ Ahi, const __nv_bfloat16* __restrict__ Alo,
    const __nv_bfloat16* __restrict__ Bhi, const __nv_bfloat16* __restrict__ Blo,
    float* __restrict__ C, int N, int K) {
    extern __shared__ char smem[];
    uint32_t sbase = (uint32_t)__cvta_generic_to_shared(smem);
    int tid = threadIdx.x;
    int lane = tid & 31, wid = tid >> 5;
    int wm = wid & 3;        // 4 warps along M
    int wn = wid >> 2;       // 2 warps along N
    int m0 = blockIdx.y * BM;
    int n0 = blockIdx.x * BN;

    float c[2][8][4];
    #pragma unroll
    for (int mi = 0; mi < 2; ++mi)
        #pragma unroll
        for (int ni = 0; ni < 8; ++ni)
            #pragma unroll
            for (int r = 0; r < 4; ++r) c[mi][ni][r] = 0.0f;

    int KT = K / BK;
    load_tiles(sbase, Ahi, Alo, Bhi, Blo, m0, n0, 0, N, K, tid);
    asm volatile("cp.async.commit_group;\n" ::: "memory");

    for (int kt = 0; kt < KT; ++kt) {
        int buf = kt & 1;
        __syncthreads();  // buffer (buf^1) free to overwrite
        if (kt + 1 < KT) {
            load_tiles(sbase + (buf ^ 1) * BUF, Ahi, Alo, Bhi, Blo,
                       m0, n0, (kt + 1) * BK, N, K, tid);
            asm volatile("cp.async.commit_group;\n" ::: "memory");
            asm volatile("cp.async.wait_group 1;\n" ::: "memory");
        } else {
            asm volatile("cp.async.wait_group 0;\n" ::: "memory");
        }
        __syncthreads();

        uint32_t sb = sbase + buf * BUF;
        uint32_t aS[2] = { sb, sb + A_TILE };                      // hi, lo
        uint32_t bS[2] = { sb + 2 * A_TILE, sb + 2 * A_TILE + B_TILE };

        #pragma unroll
        for (int p = 0; p < 3; ++p) {
            // p0: Ahi*Bhi, p1: Ahi*Blo, p2: Alo*Bhi
            uint32_t a_s = aS[p == 2 ? 1 : 0];
            uint32_t b_s = bS[p == 1 ? 1 : 0];
            #pragma unroll
            for (int ks = 0; ks < 2; ++ks) {
                uint32_t ar[2][4];
                #pragma unroll
                for (int mi = 0; mi < 2; ++mi) {
                    int row = wm * 32 + mi * 16 + (lane & 15);
                    int col = ks * 16 + (lane >> 4) * 8;
                    uint32_t addr = a_s + (uint32_t)(row * LDA_S + col) * 2;
                    asm volatile(
                        "ldmatrix.sync.aligned.m8n8.x4.shared.b16 {%0,%1,%2,%3}, [%4];\n"
                        : "=r"(ar[mi][0]), "=r"(ar[mi][1]), "=r"(ar[mi][2]), "=r"(ar[mi][3])
                        : "r"(addr));
                }
                uint32_t br[8][2];
                #pragma unroll
                for (int nj = 0; nj < 4; ++nj) {
                    int row = ks * 16 + (lane & 15);
                    int col = wn * 64 + nj * 16 + (lane >> 4) * 8;
                    uint32_t addr = b_s + (uint32_t)(row * LDB_S + col) * 2;
                    asm volatile(
                        "ldmatrix.sync.aligned.m8n8.x4.trans.shared.b16 {%0,%1,%2,%3}, [%4];\n"
                        : "=r"(br[2 * nj][0]), "=r"(br[2 * nj][1]),
                          "=r"(br[2 * nj + 1][0]), "=r"(br[2 * nj + 1][1])
                        : "r"(addr));
                }
                #pragma unroll
                for (int mi = 0; mi < 2; ++mi)
                    #pragma unroll
                    for (int ni = 0; ni < 8; ++ni)
                        asm volatile(
                            "mma.sync.aligned.m16n8k16.row.col.f32.bf16.bf16.f32 "
                            "{%0,%1,%2,%3}, {%4,%5,%6,%7}, {%8,%9}, {%0,%1,%2,%3};\n"
                            : "+f"(c[mi][ni][0]), "+f"(c[mi][ni][1]),
                              "+f"(c[mi][ni][2]), "+f"(c[mi][ni][3])
                            : "r"(ar[mi][0]), "r"(ar[mi][1]), "r"(ar[mi][2]), "r"(ar[mi][3]),
                              "r"(br[ni][0]), "r"(br[ni][1]));
            }
        }
    }

    // Epilogue: c frags -> C (fp32, row-major, ld = N)
    #pragma unroll
    for (int mi = 0; mi < 2; ++mi) {
        #pragma unroll
        for (int ni = 0; ni < 8; ++ni) {
            int row = m0 + wm * 32 + mi * 16 + (lane >> 2);
            int col = n0 + wn * 64 + ni * 8 + (lane & 3) * 2;
            float* o = C + (size_t)row * N + col;
            o[0] = c[mi][ni][0];
            o[1] = c[mi][ni][1];
            o[(size_t)8 * N]     = c[mi][ni][2];
            o[(size_t)8 * N + 1] = c[mi][ni][3];
        }
    }
}

// ---------------------------------------------------------------------------
// Launch
// ---------------------------------------------------------------------------
extern "C" void kernel_launch(void* const* d_in, const int* in_sizes, int n_in,
                              void* d_out, int out_size) {
    const float* x    = (const float*)d_in[0];
    const float* w0   = (const float*)d_in[1];
    const float* w1   = (const float*)d_in[2];
    const float* wout = (const float*)d_in[3];
    float* out = (float*)d_out;

    void *xhi, *xlo, *w0hi, *w0lo, *w1hi, *w1lo, *wohi, *wolo, *y0, *y1, *hhi, *hlo;
    cudaGetSymbolAddress(&xhi,  g_xhi);
    cudaGetSymbolAddress(&xlo,  g_xlo);
    cudaGetSymbolAddress(&w0hi, g_w0hi);
    cudaGetSymbolAddress(&w0lo, g_w0lo);
    cudaGetSymbolAddress(&w1hi, g_w1hi);
    cudaGetSymbolAddress(&w1lo, g_w1lo);
    cudaGetSymbolAddress(&wohi, g_wohi);
    cudaGetSymbolAddress(&wolo, g_wolo);
    cudaGetSymbolAddress(&y0,   g_y0);
    cudaGetSymbolAddress(&y1,   g_y1);
    cudaGetSymbolAddress(&hhi,  g_hhi);
    cudaGetSymbolAddress(&hlo,  g_hlo);

    cudaFuncSetAttribute(gemm_bf16x3,
                         cudaFuncAttributeMaxDynamicSharedMemorySize, SMEM_BYTES);

    const int nX = B_ * D_ * S_;   // 16,777,216
    const int nW = F_ * D_;        // 67,108,864
    const int nH = B_ * F_ * S_;   // 67,108,864

    // 1) split inputs into bf16 hi/lo
    split_kernel<<<nX / 4 / 256, 256>>>((const float4*)x,    (ushort4*)xhi,  (ushort4*)xlo,  nX / 4);
    split_kernel<<<nW / 4 / 256, 256>>>((const float4*)w0,   (ushort4*)w0hi, (ushort4*)w0lo, nW / 4);
    split_kernel<<<nW / 4 / 256, 256>>>((const float4*)w1,   (ushort4*)w1hi, (ushort4*)w1lo, nW / 4);
    split_kernel<<<nW / 4 / 256, 256>>>((const float4*)wout, (ushort4*)wohi, (ushort4*)wolo, nW / 4);

    // 2) layer 1: Y0 = w0 @ x_b, Y1 = w1 @ x_b  (per batch)
    dim3 g1(S_ / BN, F_ / BM);  // (16, 128)
    for (int b = 0; b < B_; ++b) {
        const __nv_bfloat16* bx_hi = (const __nv_bfloat16*)xhi + (size_t)b * D_ * S_;
        const __nv_bfloat16* bx_lo = (const __nv_bfloat16*)xlo + (size_t)b * D_ * S_;
        gemm_bf16x3<<<g1, 256, SMEM_BYTES>>>(
            (const __nv_bfloat16*)w0hi, (const __nv_bfloat16*)w0lo,
            bx_hi, bx_lo,
            (float*)y0 + (size_t)b * F_ * S_, S_, D_);
        gemm_bf16x3<<<g1, 256, SMEM_BYTES>>>(
            (const __nv_bfloat16*)w1hi, (const __nv_bfloat16*)w1lo,
            bx_hi, bx_lo,
            (float*)y1 + (size_t)b * F_ * S_, S_, D_);
    }

    // 3) H = gelu(Y0) * Y1, split to bf16 hi/lo
    h_kernel<<<nH / 4 / 256, 256>>>((const float4*)y0, (const float4*)y1,
                                    (ushort4*)hhi, (ushort4*)hlo, nH / 4);

    // 4) layer 2: out_b = w_out @ H_b
    dim3 g2(S_ / BN, D_ / BM);  // (16, 32)
    for (int b = 0; b < B_; ++b) {
        gemm_bf16x3<<<g2, 256, SMEM_BYTES>>>(
            (const __nv_bfloat16*)wohi, (const __nv_bfloat16*)wolo,
            (const __nv_bfloat16*)hhi + (size_t)b * F_ * S_,
            (const __nv_bfloat16*)hlo + (size_t)b * F_ * S_,
            out + (size_t)b * D_ * S_, S_, F_);
    }
}

// round 7
// speedup vs baseline: 2.3384x; 1.5141x over previous
#include <cuda_runtime.h>
#include <cuda_bf16.h>
#include <stdint.h>

typedef __nv_bfloat16 bf16;

// Problem dims (fixed)
#define B_ 2
#define D_ 4096
#define S_ 2048
#define F_ 16384

// ---------------------------------------------------------------------------
// Scratch (device globals; allocation-free per harness rules)
// ---------------------------------------------------------------------------
__device__ bf16  g_xThi[(size_t)B_ * S_ * D_];   // x^T per batch [S, D]
__device__ bf16  g_xTlo[(size_t)B_ * S_ * D_];
__device__ bf16  g_w0hi[(size_t)F_ * D_];
__device__ bf16  g_w0lo[(size_t)F_ * D_];
__device__ bf16  g_w1hi[(size_t)F_ * D_];
__device__ bf16  g_w1lo[(size_t)F_ * D_];
__device__ bf16  g_wohi[(size_t)D_ * F_];
__device__ bf16  g_wolo[(size_t)D_ * F_];
__device__ float g_y0[(size_t)B_ * S_ * F_];     // Y0^T [S, F]
__device__ float g_y1[(size_t)B_ * S_ * F_];
__device__ bf16  g_hhi[(size_t)B_ * S_ * F_];    // H^T  [S, F]
__device__ bf16  g_hlo[(size_t)B_ * S_ * F_];
__device__ float g_oT[(size_t)B_ * S_ * D_];     // out^T [S, D]

// ---------------------------------------------------------------------------
// PTX helpers (sm_80-era only; NO tcgen05 — ptxas targets plain sm_103)
// ---------------------------------------------------------------------------
__device__ __forceinline__ void cp16(uint32_t s, const void* g) {
    asm volatile("cp.async.cg.shared.global [%0], [%1], 16;\n" :: "r"(s), "l"(g));
}

__device__ __forceinline__ void ldsm_x4(uint32_t addr, uint32_t* r) {
    asm volatile(
        "ldmatrix.sync.aligned.m8n8.x4.shared.b16 {%0,%1,%2,%3}, [%4];\n"
        : "=r"(r[0]), "=r"(r[1]), "=r"(r[2]), "=r"(r[3]) : "r"(addr));
}

__device__ __forceinline__ void mma_bf16(float* c, const uint32_t* a,
                                         uint32_t b0, uint32_t b1) {
    asm volatile(
        "mma.sync.aligned.m16n8k16.row.col.f32.bf16.bf16.f32 "
        "{%0,%1,%2,%3}, {%4,%5,%6,%7}, {%8,%9}, {%0,%1,%2,%3};\n"
        : "+f"(c[0]), "+f"(c[1]), "+f"(c[2]), "+f"(c[3])
        : "r"(a[0]), "r"(a[1]), "r"(a[2]), "r"(a[3]), "r"(b0), "r"(b1));
}

#define SWZ(x) ((x) ^ (((x) >> 3) & 0x70))

// ---------------------------------------------------------------------------
// bf16x3 GEMM (mma.sync):  C[M,N] fp32 = (Ahi+Alo)[M,K] @ (Bhi+Blo)[N,K]^T
// Both operands K-major row-major; 3 products Ahi*Bhi + Ahi*Blo + Alo*Bhi.
// CTA tile 128x128, BK=64, 3-stage cp.async pipeline, SW128 swizzle.
// 8 warps as 2(m) x 4(n): warp tile 64x32. Frags loaded once per k16 slice,
// reused across all 3 products.
// ---------------------------------------------------------------------------
constexpr int BM = 128, BN = 128, BK = 64;
constexpr int SUB   = BM * 128;             // 16384 B per sub-tile (Ahi/Alo/Bhi/Blo)
constexpr int STAGE = 4 * SUB;              // 65536 B
constexpr int NSTG  = 3;
constexpr int SMEM_TOT = NSTG * STAGE;      // 196608 B

struct GemmArgs {
    const bf16 *Ah, *Al;
    unsigned long long aStride;              // elements per batch
    const bf16 *Bh0, *Bl0, *Bh1, *Bl1;
    float *C0, *C1;
    unsigned long long cStride;
    int N, K, nw;
};

__device__ __forceinline__ void load_stage(
    uint32_t st, const bf16* __restrict__ Ah, const bf16* __restrict__ Al,
    const bf16* __restrict__ Bh, const bf16* __restrict__ Bl,
    size_t m0, size_t n0, int k0, int K, int tid) {
    #pragma unroll
    for (int i = 0; i < 4; ++i) {
        int c = tid + i * 256;
        int r = c >> 3, cb = (c & 7) * 16;
        size_t gbyte = (((m0 + r) * (size_t)K + k0) << 1) + cb;
        uint32_t s = SWZ((uint32_t)(r * 128 + cb));
        cp16(st + s,       (const char*)Ah + gbyte);
        cp16(st + SUB + s, (const char*)Al + gbyte);
    }
    #pragma unroll
    for (int i = 0; i < 4; ++i) {
        int c = tid + i * 256;
        int r = c >> 3, cb = (c & 7) * 16;
        size_t gbyte = (((n0 + r) * (size_t)K + k0) << 1) + cb;
        uint32_t s = SWZ((uint32_t)(r * 128 + cb));
        cp16(st + 2 * SUB + s, (const char*)Bh + gbyte);
        cp16(st + 3 * SUB + s, (const char*)Bl + gbyte);
    }
}

__global__ void __launch_bounds__(256, 1) gemm_mma(GemmArgs g) {
    extern __shared__ char smem[];
    uint32_t sb = (uint32_t)__cvta_generic_to_shared(smem);
    int tid = threadIdx.x, wid = tid >> 5, lane = tid & 31;
    int wm = wid >> 2;        // 2 warps along M (64 rows each)
    int wn = wid & 3;         // 4 warps along N (32 cols each)

    int z = blockIdx.z;
    int b = z / g.nw, w = z % g.nw;
    const bf16* Ah = g.Ah + (size_t)b * g.aStride;
    const bf16* Al = g.Al + (size_t)b * g.aStride;
    const bf16* Bh = w ? g.Bh1 : g.Bh0;
    const bf16* Bl = w ? g.Bl1 : g.Bl0;
    float* C = (w ? g.C1 : g.C0) + (size_t)b * g.cStride;
    size_t m0 = (size_t)blockIdx.x * BM;
    size_t n0 = (size_t)blockIdx.y * BN;
    const int K = g.K, N = g.N;
    const int KT = K / BK;

    float c[4][4][4];
    #pragma unroll
    for (int mi = 0; mi < 4; ++mi)
        #pragma unroll
        for (int ni = 0; ni < 4; ++ni)
            #pragma unroll
            for (int r = 0; r < 4; ++r) c[mi][ni][r] = 0.0f;

    // Prologue: fill stages 0 and 1
    load_stage(sb,         Ah, Al, Bh, Bl, m0, n0, 0,  K, tid);
    asm volatile("cp.async.commit_group;\n" ::: "memory");
    load_stage(sb + STAGE, Ah, Al, Bh, Bl, m0, n0, BK, K, tid);
    asm volatile("cp.async.commit_group;\n" ::: "memory");

    // Lane -> smem offsets (tile-local, swizzled at use)
    int aRow = wm * 64 + (lane & 15);            // + mi*16
    int aCol = (lane >> 4) * 16;                 // + ks*32 (bytes)
    int bRow = wn * 32 + (lane & 7) + ((lane >> 4) << 3);  // + nj*16
    int bCol = ((lane >> 3) & 1) * 16;           // + ks*32 (bytes)

    for (int kt = 0; kt < KT; ++kt) {
        if (kt + 1 < KT) asm volatile("cp.async.wait_group 1;\n" ::: "memory");
        else             asm volatile("cp.async.wait_group 0;\n" ::: "memory");
        __syncthreads();

        uint32_t st = sb + (kt % NSTG) * STAGE;

        // Prefetch stage kt+2 (its buffer was consumed at iteration kt-1)
        if (kt + 2 < KT) {
            load_stage(sb + ((kt + 2) % NSTG) * STAGE, Ah, Al, Bh, Bl,
                       m0, n0, (kt + 2) * BK, K, tid);
            asm volatile("cp.async.commit_group;\n" ::: "memory");
        }

        #pragma unroll
        for (int ks = 0; ks < 4; ++ks) {
            uint32_t ah[4][4], al[4][4], bh[2][4], bl[2][4];
            #pragma unroll
            for (int mi = 0; mi < 4; ++mi) {
                uint32_t off = SWZ((uint32_t)((aRow + mi * 16) * 128 + ks * 32 + aCol));
                ldsm_x4(st + off,       ah[mi]);
                ldsm_x4(st + SUB + off, al[mi]);
            }
            #pragma unroll
            for (int nj = 0; nj < 2; ++nj) {
                uint32_t off = SWZ((uint32_t)((bRow + nj * 16) * 128 + ks * 32 + bCol));
                ldsm_x4(st + 2 * SUB + off, bh[nj]);
                ldsm_x4(st + 3 * SUB + off, bl[nj]);
            }
            // 3 products, frags reused
            #pragma unroll
            for (int mi = 0; mi < 4; ++mi) {
                #pragma unroll
                for (int ni = 0; ni < 4; ++ni) {
                    int nj = ni >> 1, pr = (ni & 1) * 2;
                    mma_bf16(c[mi][ni], ah[mi], bh[nj][pr], bh[nj][pr + 1]);
                    mma_bf16(c[mi][ni], ah[mi], bl[nj][pr], bl[nj][pr + 1]);
                    mma_bf16(c[mi][ni], al[mi], bh[nj][pr], bh[nj][pr + 1]);
                }
            }
        }
        __syncthreads();
    }

    // Epilogue: fragment -> C (fp32 row-major, ld = N)
    #pragma unroll
    for (int mi = 0; mi < 4; ++mi) {
        #pragma unroll
        for (int ni = 0; ni < 4; ++ni) {
            size_t row = m0 + wm * 64 + mi * 16 + (lane >> 2);
            size_t col = n0 + wn * 32 + ni * 8 + (lane & 3) * 2;
            float2* p0 = (float2*)(C + row * (size_t)N + col);
            float2* p1 = (float2*)(C + (row + 8) * (size_t)N + col);
            *p0 = make_float2(c[mi][ni][0], c[mi][ni][1]);
            *p1 = make_float2(c[mi][ni][2], c[mi][ni][3]);
        }
    }
}

// ---------------------------------------------------------------------------
// Elementwise kernels
// ---------------------------------------------------------------------------
__global__ void split_kernel(const float4* __restrict__ in,
                             ushort4* __restrict__ hi,
                             ushort4* __restrict__ lo, int n4) {
    int i = blockIdx.x * blockDim.x + threadIdx.x;
    if (i >= n4) return;
    float4 v = in[i];
    __nv_bfloat16 h0 = __float2bfloat16(v.x), h1 = __float2bfloat16(v.y);
    __nv_bfloat16 h2 = __float2bfloat16(v.z), h3 = __float2bfloat16(v.w);
    ushort4 H = { __bfloat16_as_ushort(h0), __bfloat16_as_ushort(h1),
                  __bfloat16_as_ushort(h2), __bfloat16_as_ushort(h3) };
    hi[i] = H;
    ushort4 L = { __bfloat16_as_ushort(__float2bfloat16(v.x - __bfloat162float(h0))),
                  __bfloat16_as_ushort(__float2bfloat16(v.y - __bfloat162float(h1))),
                  __bfloat16_as_ushort(__float2bfloat16(v.z - __bfloat162float(h2))),
                  __bfloat16_as_ushort(__float2bfloat16(v.w - __bfloat162float(h3))) };
    lo[i] = L;
}

__device__ __forceinline__ float gelu_exact(float v) {
    return 0.5f * v * (1.0f + erff(v * 0.70710678118654752440f));
}

__global__ void h_kernel(const float4* __restrict__ y0,
                         const float4* __restrict__ y1,
                         ushort4* __restrict__ hhi,
                         ushort4* __restrict__ hlo, int n4) {
    int i = blockIdx.x * blockDim.x + threadIdx.x;
    if (i >= n4) return;
    float4 a = y0[i];
    float4 bb = y1[i];
    float v0 = gelu_exact(a.x) * bb.x;
    float v1 = gelu_exact(a.y) * bb.y;
    float v2 = gelu_exact(a.z) * bb.z;
    float v3 = gelu_exact(a.w) * bb.w;
    __nv_bfloat16 h0 = __float2bfloat16(v0), h1 = __float2bfloat16(v1);
    __nv_bfloat16 h2 = __float2bfloat16(v2), h3 = __float2bfloat16(v3);
    ushort4 H = { __bfloat16_as_ushort(h0), __bfloat16_as_ushort(h1),
                  __bfloat16_as_ushort(h2), __bfloat16_as_ushort(h3) };
    hhi[i] = H;
    ushort4 L = { __bfloat16_as_ushort(__float2bfloat16(v0 - __bfloat162float(h0))),
                  __bfloat16_as_ushort(__float2bfloat16(v1 - __bfloat162float(h1))),
                  __bfloat16_as_ushort(__float2bfloat16(v2 - __bfloat162float(h2))),
                  __bfloat16_as_ushort(__float2bfloat16(v3 - __bfloat162float(h3))) };
    hlo[i] = L;
}

// Transpose fp32 [R,C] -> bf16 hi/lo [C,R]  (per batch via blockIdx.z)
__global__ void transpose_split(const float* __restrict__ in,
                                bf16* __restrict__ ohi, bf16* __restrict__ olo,
                                int R, int C) {
    __shared__ float t[32][33];
    size_t base = (size_t)blockIdx.z * R * C;
    int c0 = blockIdx.x * 32, r0 = blockIdx.y * 32;
    int tx = threadIdx.x, ty = threadIdx.y;
    #pragma unroll
    for (int i = 0; i < 4; ++i)
        t[ty + 8 * i][tx] = in[base + (size_t)(r0 + ty + 8 * i) * C + c0 + tx];
    __syncthreads();
    #pragma unroll
    for (int i = 0; i < 4; ++i) {
        float v = t[tx][ty + 8 * i];
        bf16 h = __float2bfloat16(v);
        size_t o = base + (size_t)(c0 + ty + 8 * i) * R + r0 + tx;
        ohi[o] = h;
        olo[o] = __float2bfloat16(v - __bfloat162float(h));
    }
}

// Transpose fp32 [R,C] -> fp32 [C,R]  (per batch via blockIdx.z)
__global__ void transpose_f32(const float* __restrict__ in, float* __restrict__ out,
                              int R, int C) {
    __shared__ float t[32][33];
    size_t base = (size_t)blockIdx.z * R * C;
    int c0 = blockIdx.x * 32, r0 = blockIdx.y * 32;
    int tx = threadIdx.x, ty = threadIdx.y;
    #pragma unroll
    for (int i = 0; i < 4; ++i)
        t[ty + 8 * i][tx] = in[base + (size_t)(r0 + ty + 8 * i) * C + c0 + tx];
    __syncthreads();
    #pragma unroll
    for (int i = 0; i < 4; ++i)
        out[base + (size_t)(c0 + ty + 8 * i) * R + r0 + tx] = t[tx][ty + 8 * i];
}

// ---------------------------------------------------------------------------
// Launch
// ---------------------------------------------------------------------------
extern "C" void kernel_launch(void* const* d_in, const int* in_sizes, int n_in,
                              void* d_out, int out_size) {
    const float* x    = (const float*)d_in[0];
    const float* w0   = (const float*)d_in[1];
    const float* w1   = (const float*)d_in[2];
    const float* wout = (const float*)d_in[3];
    float* out = (float*)d_out;

    void *xThi, *xTlo, *w0hi, *w0lo, *w1hi, *w1lo, *wohi, *wolo, *y0, *y1, *hhi, *hlo, *oT;
    cudaGetSymbolAddress(&xThi, g_xThi);
    cudaGetSymbolAddress(&xTlo, g_xTlo);
    cudaGetSymbolAddress(&w0hi, g_w0hi);
    cudaGetSymbolAddress(&w0lo, g_w0lo);
    cudaGetSymbolAddress(&w1hi, g_w1hi);
    cudaGetSymbolAddress(&w1lo, g_w1lo);
    cudaGetSymbolAddress(&wohi, g_wohi);
    cudaGetSymbolAddress(&wolo, g_wolo);
    cudaGetSymbolAddress(&y0,   g_y0);
    cudaGetSymbolAddress(&y1,   g_y1);
    cudaGetSymbolAddress(&hhi,  g_hhi);
    cudaGetSymbolAddress(&hlo,  g_hlo);
    cudaGetSymbolAddress(&oT,   g_oT);

    cudaFuncSetAttribute(gemm_mma, cudaFuncAttributeMaxDynamicSharedMemorySize, SMEM_TOT);

    const int nW = F_ * D_;        // 67,108,864
    const int nH = B_ * F_ * S_;   // 67,108,864

    // 1) transpose+split x: [b][D][S] fp32 -> [b][S][D] bf16 hi/lo
    {
        dim3 blk(32, 8), grd(S_ / 32, D_ / 32, B_);
        transpose_split<<<grd, blk>>>(x, (bf16*)xThi, (bf16*)xTlo, D_, S_);
    }
    // 2) split weights (K-major already)
    split_kernel<<<nW / 4 / 256, 256>>>((const float4*)w0,   (ushort4*)w0hi, (ushort4*)w0lo, nW / 4);
    split_kernel<<<nW / 4 / 256, 256>>>((const float4*)w1,   (ushort4*)w1hi, (ushort4*)w1lo, nW / 4);
    split_kernel<<<nW / 4 / 256, 256>>>((const float4*)wout, (ushort4*)wohi, (ushort4*)wolo, nW / 4);

    // 3) layer 1: Y0^T[S,F] = X^T W0^T, Y1^T = X^T W1^T  (z = batch*2 + weight)
    {
        GemmArgs a;
        a.Ah = (const bf16*)xThi;  a.Al = (const bf16*)xTlo;
        a.aStride = (unsigned long long)S_ * D_;
        a.Bh0 = (const bf16*)w0hi; a.Bl0 = (const bf16*)w0lo;
        a.Bh1 = (const bf16*)w1hi; a.Bl1 = (const bf16*)w1lo;
        a.C0 = (float*)y0; a.C1 = (float*)y1;
        a.cStride = (unsigned long long)S_ * F_;
        a.N = F_; a.K = D_; a.nw = 2;
        dim3 grd(S_ / BM, F_ / BN, B_ * 2);   // (16, 128, 4)
        gemm_mma<<<grd, 256, SMEM_TOT>>>(a);
    }

    // 4) H^T = gelu(Y0^T) * Y1^T, split to bf16 hi/lo
    h_kernel<<<nH / 4 / 256, 256>>>((const float4*)y0, (const float4*)y1,
                                    (ushort4*)hhi, (ushort4*)hlo, nH / 4);

    // 5) layer 2: out^T[S,D] = H^T Wout^T
    {
        GemmArgs a;
        a.Ah = (const bf16*)hhi;  a.Al = (const bf16*)hlo;
        a.aStride = (unsigned long long)S_ * F_;
        a.Bh0 = (const bf16*)wohi; a.Bl0 = (const bf16*)wolo;
        a.Bh1 = (const bf16*)wohi; a.Bl1 = (const bf16*)wolo;
        a.C0 = (float*)oT; a.C1 = (float*)oT;
        a.cStride = (unsigned long long)S_ * D_;
        a.N = D_; a.K = F_; a.nw = 1;
        dim3 grd(S_ / BM, D_ / BN, B_);       // (16, 32, 2)
        gemm_mma<<<grd, 256, SMEM_TOT>>>(a);
    }

    // 6) transpose out^T [b][S][D] -> out [b][D][S] fp32
    {
        dim3 blk(32, 8), grd(D_ / 32, S_ / 32, B_);
        transpose_f32<<<grd, blk>>>((const float*)oT, out, S_, D_);
    }
}

// round 8
// speedup vs baseline: 2.3622x; 1.0102x over previous
#include <cuda_runtime.h>
#include <cuda_bf16.h>
#include <stdint.h>

typedef __nv_bfloat16 bf16;

// Problem dims (fixed)
#define B_ 2
#define D_ 4096
#define S_ 2048
#define F_ 16384

// ---------------------------------------------------------------------------
// Scratch (device globals; allocation-free per harness rules)
// ---------------------------------------------------------------------------
__device__ bf16  g_xThi[(size_t)B_ * S_ * D_];   // x^T per batch [S, D]
__device__ bf16  g_xTlo[(size_t)B_ * S_ * D_];
__device__ bf16  g_w0hi[(size_t)F_ * D_];
__device__ bf16  g_w0lo[(size_t)F_ * D_];
__device__ bf16  g_w1hi[(size_t)F_ * D_];
__device__ bf16  g_w1lo[(size_t)F_ * D_];
__device__ bf16  g_wohi[(size_t)D_ * F_];
__device__ bf16  g_wolo[(size_t)D_ * F_];
__device__ bf16  g_hhi[(size_t)B_ * S_ * F_];    // H^T  [S, F]
__device__ bf16  g_hlo[(size_t)B_ * S_ * F_];
__device__ float g_oT[(size_t)B_ * S_ * D_];     // out^T [S, D]

// ---------------------------------------------------------------------------
// PTX helpers (sm_80-era only; NO tcgen05 — ptxas targets plain sm_103)
// ---------------------------------------------------------------------------
__device__ __forceinline__ void cp16(uint32_t s, const void* g) {
    asm volatile("cp.async.cg.shared.global [%0], [%1], 16;\n" :: "r"(s), "l"(g));
}

__device__ __forceinline__ void ldsm_x4(uint32_t addr, uint32_t* r) {
    asm volatile(
        "ldmatrix.sync.aligned.m8n8.x4.shared.b16 {%0,%1,%2,%3}, [%4];\n"
        : "=r"(r[0]), "=r"(r[1]), "=r"(r[2]), "=r"(r[3]) : "r"(addr));
}

__device__ __forceinline__ void mma_bf16(float* c, const uint32_t* a,
                                         uint32_t b0, uint32_t b1) {
    asm volatile(
        "mma.sync.aligned.m16n8k16.row.col.f32.bf16.bf16.f32 "
        "{%0,%1,%2,%3}, {%4,%5,%6,%7}, {%8,%9}, {%0,%1,%2,%3};\n"
        : "+f"(c[0]), "+f"(c[1]), "+f"(c[2]), "+f"(c[3])
        : "r"(a[0]), "r"(a[1]), "r"(a[2]), "r"(a[3]), "r"(b0), "r"(b1));
}

__device__ __forceinline__ float gelu_exact(float v) {
    return 0.5f * v * (1.0f + erff(v * 0.70710678118654752440f));
}

#define SWZ(x) ((x) ^ (((x) >> 3) & 0x70))

// ===========================================================================
// GEMM1 fused: per CTA output tile 128(S) x 64(F); warps 0-3 compute
// gate = (xT)(w0^T), warps 4-7 compute up = (xT)(w1^T) for the SAME tile.
// bf16x3 products, fp32 accum. Epilogue: h = gelu(gate)*up -> bf16 hi/lo.
// 3-stage cp.async pipeline, BK=64, SW128 swizzle, ONE barrier per stage.
// ===========================================================================
constexpr int BK = 64;
constexpr int G1_STAGE = 65536;                  // Ah16K Al16K B0h8K B0l8K B1h8K B1l8K
constexpr int NSTG = 3;
constexpr int G1_SMEM = NSTG * G1_STAGE;         // 196608

__device__ __forceinline__ void g1_load_stage(
    uint32_t st, const bf16* __restrict__ Ah, const bf16* __restrict__ Al,
    const bf16* __restrict__ W0h, const bf16* __restrict__ W0l,
    const bf16* __restrict__ W1h, const bf16* __restrict__ W1l,
    size_t m0, size_t n0, int k0, int tid) {
    const int K = D_;
    // A: 128 rows x 128B, hi+lo = 2048 chunks
    #pragma unroll
    for (int i = 0; i < 8; ++i) {
        int sub = i >> 2;                 // 0=hi, 1=lo (compile-time)
        int cc  = (i & 3) * 256 + tid;    // 0..1023
        int r = cc >> 3, cb = (cc & 7) * 16;
        size_t gbyte = (((m0 + r) * (size_t)K + k0) << 1) + cb;
        uint32_t s = SWZ((uint32_t)(r * 128 + cb));
        cp16(st + sub * 16384 + s, (const char*)(sub ? Al : Ah) + gbyte);
    }
    // B: 4 subtiles (w0h, w0l, w1h, w1l), each 64 rows x 128B = 512 chunks
    #pragma unroll
    for (int i = 0; i < 8; ++i) {
        int sub = i >> 1;                 // compile-time
        int cc  = (i & 1) * 256 + tid;    // 0..511
        int r = cc >> 3, cb = (cc & 7) * 16;
        size_t gbyte = (((n0 + r) * (size_t)K + k0) << 1) + cb;
        uint32_t s = SWZ((uint32_t)(r * 128 + cb));
        const bf16* p = (sub == 0) ? W0h : (sub == 1) ? W0l : (sub == 2) ? W1h : W1l;
        cp16(st + 32768 + sub * 8192 + s, (const char*)p + gbyte);
    }
}

__global__ void __launch_bounds__(256, 1) gemm1_fused(
    const bf16* __restrict__ Ah, const bf16* __restrict__ Al,
    const bf16* __restrict__ W0h, const bf16* __restrict__ W0l,
    const bf16* __restrict__ W1h, const bf16* __restrict__ W1l,
    bf16* __restrict__ Hhi, bf16* __restrict__ Hlo) {
    extern __shared__ char smem[];
    uint32_t sb = (uint32_t)__cvta_generic_to_shared(smem);
    int tid = threadIdx.x, wid = tid >> 5, lane = tid & 31;
    int grp = wid >> 2;        // 0 = gate(w0), 1 = up(w1)
    int wg  = wid & 3;
    int wm  = wg >> 1;         // 2 warps along M (64 rows each)
    int wn  = wg & 1;          // 2 warps along N (32 cols each)

    int b = blockIdx.z;
    const bf16* xh = Ah + (size_t)b * S_ * D_;
    const bf16* xl = Al + (size_t)b * S_ * D_;
    bf16* Oh = Hhi + (size_t)b * S_ * F_;
    bf16* Ol = Hlo + (size_t)b * S_ * F_;
    size_t m0 = (size_t)blockIdx.x * 128;
    size_t n0 = (size_t)blockIdx.y * 64;
    const int KT = D_ / BK;    // 64

    float c[4][4][4];
    #pragma unroll
    for (int mi = 0; mi < 4; ++mi)
        #pragma unroll
        for (int ni = 0; ni < 4; ++ni)
            #pragma unroll
            for (int r = 0; r < 4; ++r) c[mi][ni][r] = 0.0f;

    g1_load_stage(sb,            xh, xl, W0h, W0l, W1h, W1l, m0, n0, 0,  tid);
    asm volatile("cp.async.commit_group;\n" ::: "memory");
    g1_load_stage(sb + G1_STAGE, xh, xl, W0h, W0l, W1h, W1l, m0, n0, BK, tid);
    asm volatile("cp.async.commit_group;\n" ::: "memory");

    int aRow = wm * 64 + (lane & 15);
    int aCol = (lane >> 4) * 16;
    int bRow = wn * 32 + (lane & 7) + ((lane >> 4) << 3);
    int bCol = ((lane >> 3) & 1) * 16;
    uint32_t bBase = 32768 + grp * 16384;   // this group's B (hi at +0, lo at +8192)

    for (int kt = 0; kt < KT; ++kt) {
        if (kt + 1 < KT) asm volatile("cp.async.wait_group 1;\n" ::: "memory");
        else             asm volatile("cp.async.wait_group 0;\n" ::: "memory");
        __syncthreads();   // sole barrier per stage (prefetch below is safe: all
                           // warps finished reading the target stage last iter)
        uint32_t st = sb + (kt % NSTG) * G1_STAGE;
        if (kt + 2 < KT) {
            g1_load_stage(sb + ((kt + 2) % NSTG) * G1_STAGE, xh, xl,
                          W0h, W0l, W1h, W1l, m0, n0, (kt + 2) * BK, tid);
            asm volatile("cp.async.commit_group;\n" ::: "memory");
        }

        #pragma unroll
        for (int ks = 0; ks < 4; ++ks) {
            uint32_t ah[4][4], al[4][4], bh[2][4], bl[2][4];
            #pragma unroll
            for (int mi = 0; mi < 4; ++mi) {
                uint32_t off = SWZ((uint32_t)((aRow + mi * 16) * 128 + ks * 32 + aCol));
                ldsm_x4(st + off,         ah[mi]);
                ldsm_x4(st + 16384 + off, al[mi]);
            }
            #pragma unroll
            for (int nj = 0; nj < 2; ++nj) {
                uint32_t off = SWZ((uint32_t)((bRow + nj * 16) * 128 + ks * 32 + bCol));
                ldsm_x4(st + bBase + off,        bh[nj]);
                ldsm_x4(st + bBase + 8192 + off, bl[nj]);
            }
            #pragma unroll
            for (int mi = 0; mi < 4; ++mi) {
                #pragma unroll
                for (int ni = 0; ni < 4; ++ni) {
                    int nj = ni >> 1, pr = (ni & 1) * 2;
                    mma_bf16(c[mi][ni], ah[mi], bh[nj][pr], bh[nj][pr + 1]);
                    mma_bf16(c[mi][ni], ah[mi], bl[nj][pr], bl[nj][pr + 1]);
                    mma_bf16(c[mi][ni], al[mi], bh[nj][pr], bh[nj][pr + 1]);
                }
            }
        }
    }

    // ---- Fused epilogue: h = gelu(gate) * up, split bf16 hi/lo ----
    __syncthreads();                         // smem stages now reusable
    float* gsm = (float*)smem;               // 4 warps x 2048 floats = 32KB
    int slotBase = wg * 2048 + lane;         // lane-major: conflict-free
    if (grp == 0) {
        #pragma unroll
        for (int mi = 0; mi < 4; ++mi)
            #pragma unroll
            for (int ni = 0; ni < 4; ++ni)
                #pragma unroll
                for (int r = 0; r < 4; ++r)
                    gsm[slotBase + (mi * 16 + ni * 4 + r) * 32] = c[mi][ni][r];
    }
    __syncthreads();
    if (grp == 1) {
        #pragma unroll
        for (int mi = 0; mi < 4; ++mi) {
            #pragma unroll
            for (int ni = 0; ni < 4; ++ni) {
                float h[4];
                #pragma unroll
                for (int r = 0; r < 4; ++r) {
                    float gate = gsm[slotBase + (mi * 16 + ni * 4 + r) * 32];
                    h[r] = gelu_exact(gate) * c[mi][ni][r];
                }
                size_t row = m0 + wm * 64 + mi * 16 + (lane >> 2);
                size_t col = n0 + wn * 32 + ni * 8 + (lane & 3) * 2;
                #pragma unroll
                for (int half = 0; half < 2; ++half) {
                    float v0 = h[half * 2], v1 = h[half * 2 + 1];
                    bf16 h0 = __float2bfloat16(v0), h1 = __float2bfloat16(v1);
                    __nv_bfloat162 hi2 = { h0, h1 };
                    __nv_bfloat162 lo2 = { __float2bfloat16(v0 - __bfloat162float(h0)),
                                           __float2bfloat16(v1 - __bfloat162float(h1)) };
                    size_t o = (row + half * 8) * (size_t)F_ + col;
                    *(__nv_bfloat162*)(Oh + o) = hi2;
                    *(__nv_bfloat162*)(Ol + o) = lo2;
                }
            }
        }
    }
}

// ===========================================================================
// Generic bf16x3 GEMM (GEMM2): C[M,N] fp32 = (Ahi+Alo)[M,K] @ (Bhi+Blo)[N,K]^T
// CTA 128x128, BK=64, 3 stages, one barrier per stage.
// ===========================================================================
constexpr int BM = 128, BN = 128;
constexpr int SUB   = BM * 128;             // 16384 B per sub-tile
constexpr int STAGE = 4 * SUB;              // 65536 B
constexpr int SMEM_TOT = NSTG * STAGE;      // 196608 B

__device__ __forceinline__ void load_stage(
    uint32_t st, const bf16* __restrict__ Ah, const bf16* __restrict__ Al,
    const bf16* __restrict__ Bh, const bf16* __restrict__ Bl,
    size_t m0, size_t n0, int k0, int K, int tid) {
    #pragma unroll
    for (int i = 0; i < 4; ++i) {
        int c = tid + i * 256;
        int r = c >> 3, cb = (c & 7) * 16;
        size_t gbyte = (((m0 + r) * (size_t)K + k0) << 1) + cb;
        uint32_t s = SWZ((uint32_t)(r * 128 + cb));
        cp16(st + s,       (const char*)Ah + gbyte);
        cp16(st + SUB + s, (const char*)Al + gbyte);
    }
    #pragma unroll
    for (int i = 0; i < 4; ++i) {
        int c = tid + i * 256;
        int r = c >> 3, cb = (c & 7) * 16;
        size_t gbyte = (((n0 + r) * (size_t)K + k0) << 1) + cb;
        uint32_t s = SWZ((uint32_t)(r * 128 + cb));
        cp16(st + 2 * SUB + s, (const char*)Bh + gbyte);
        cp16(st + 3 * SUB + s, (const char*)Bl + gbyte);
    }
}

__global__ void __launch_bounds__(256, 1) gemm_mma(
    const bf16* __restrict__ gAh, const bf16* __restrict__ gAl,
    const bf16* __restrict__ Bh, const bf16* __restrict__ Bl,
    float* __restrict__ gC, int N, int K,
    unsigned long long aStride, unsigned long long cStride) {
    extern __shared__ char smem[];
    uint32_t sb = (uint32_t)__cvta_generic_to_shared(smem);
    int tid = threadIdx.x, wid = tid >> 5, lane = tid & 31;
    int wm = wid >> 2;        // 2 warps along M (64 rows each)
    int wn = wid & 3;         // 4 warps along N (32 cols each)

    int b = blockIdx.z;
    const bf16* Ah = gAh + (size_t)b * aStride;
    const bf16* Al = gAl + (size_t)b * aStride;
    float* C = gC + (size_t)b * cStride;
    size_t m0 = (size_t)blockIdx.x * BM;
    size_t n0 = (size_t)blockIdx.y * BN;
    const int KT = K / BK;

    float c[4][4][4];
    #pragma unroll
    for (int mi = 0; mi < 4; ++mi)
        #pragma unroll
        for (int ni = 0; ni < 4; ++ni)
            #pragma unroll
            for (int r = 0; r < 4; ++r) c[mi][ni][r] = 0.0f;

    load_stage(sb,         Ah, Al, Bh, Bl, m0, n0, 0,  K, tid);
    asm volatile("cp.async.commit_group;\n" ::: "memory");
    load_stage(sb + STAGE, Ah, Al, Bh, Bl, m0, n0, BK, K, tid);
    asm volatile("cp.async.commit_group;\n" ::: "memory");

    int aRow = wm * 64 + (lane & 15);
    int aCol = (lane >> 4) * 16;
    int bRow = wn * 32 + (lane & 7) + ((lane >> 4) << 3);
    int bCol = ((lane >> 3) & 1) * 16;

    for (int kt = 0; kt < KT; ++kt) {
        if (kt + 1 < KT) asm volatile("cp.async.wait_group 1;\n" ::: "memory");
        else             asm volatile("cp.async.wait_group 0;\n" ::: "memory");
        __syncthreads();   // sole barrier per stage

        uint32_t st = sb + (kt % NSTG) * STAGE;
        if (kt + 2 < KT) {
            load_stage(sb + ((kt + 2) % NSTG) * STAGE, Ah, Al, Bh, Bl,
                       m0, n0, (kt + 2) * BK, K, tid);
            asm volatile("cp.async.commit_group;\n" ::: "memory");
        }

        #pragma unroll
        for (int ks = 0; ks < 4; ++ks) {
            uint32_t ah[4][4], al[4][4], bh[2][4], bl[2][4];
            #pragma unroll
            for (int mi = 0; mi < 4; ++mi) {
                uint32_t off = SWZ((uint32_t)((aRow + mi * 16) * 128 + ks * 32 + aCol));
                ldsm_x4(st + off,       ah[mi]);
                ldsm_x4(st + SUB + off, al[mi]);
            }
            #pragma unroll
            for (int nj = 0; nj < 2; ++nj) {
                uint32_t off = SWZ((uint32_t)((bRow + nj * 16) * 128 + ks * 32 + bCol));
                ldsm_x4(st + 2 * SUB + off, bh[nj]);
                ldsm_x4(st + 3 * SUB + off, bl[nj]);
            }
            #pragma unroll
            for (int mi = 0; mi < 4; ++mi) {
                #pragma unroll
                for (int ni = 0; ni < 4; ++ni) {
                    int nj = ni >> 1, pr = (ni & 1) * 2;
                    mma_bf16(c[mi][ni], ah[mi], bh[nj][pr], bh[nj][pr + 1]);
                    mma_bf16(c[mi][ni], ah[mi], bl[nj][pr], bl[nj][pr + 1]);
                    mma_bf16(c[mi][ni], al[mi], bh[nj][pr], bh[nj][pr + 1]);
                }
            }
        }
    }

    #pragma unroll
    for (int mi = 0; mi < 4; ++mi) {
        #pragma unroll
        for (int ni = 0; ni < 4; ++ni) {
            size_t row = m0 + wm * 64 + mi * 16 + (lane >> 2);
            size_t col = n0 + wn * 32 + ni * 8 + (lane & 3) * 2;
            float2* p0 = (float2*)(C + row * (size_t)N + col);
            float2* p1 = (float2*)(C + (row + 8) * (size_t)N + col);
            *p0 = make_float2(c[mi][ni][0], c[mi][ni][1]);
            *p1 = make_float2(c[mi][ni][2], c[mi][ni][3]);
        }
    }
}

// ---------------------------------------------------------------------------
// Elementwise kernels
// ---------------------------------------------------------------------------
__global__ void split_kernel(const float4* __restrict__ in,
                             ushort4* __restrict__ hi,
                             ushort4* __restrict__ lo, int n4) {
    int i = blockIdx.x * blockDim.x + threadIdx.x;
    if (i >= n4) return;
    float4 v = in[i];
    __nv_bfloat16 h0 = __float2bfloat16(v.x), h1 = __float2bfloat16(v.y);
    __nv_bfloat16 h2 = __float2bfloat16(v.z), h3 = __float2bfloat16(v.w);
    ushort4 H = { __bfloat16_as_ushort(h0), __bfloat16_as_ushort(h1),
                  __bfloat16_as_ushort(h2), __bfloat16_as_ushort(h3) };
    hi[i] = H;
    ushort4 L = { __bfloat16_as_ushort(__float2bfloat16(v.x - __bfloat162float(h0))),
                  __bfloat16_as_ushort(__float2bfloat16(v.y - __bfloat162float(h1))),
                  __bfloat16_as_ushort(__float2bfloat16(v.z - __bfloat162float(h2))),
                  __bfloat16_as_ushort(__float2bfloat16(v.w - __bfloat162float(h3))) };
    lo[i] = L;
}

// Transpose fp32 [R,C] -> bf16 hi/lo [C,R]  (per batch via blockIdx.z)
__global__ void transpose_split(const float* __restrict__ in,
                                bf16* __restrict__ ohi, bf16* __restrict__ olo,
                                int R, int C) {
    __shared__ float t[32][33];
    size_t base = (size_t)blockIdx.z * R * C;
    int c0 = blockIdx.x * 32, r0 = blockIdx.y * 32;
    int tx = threadIdx.x, ty = threadIdx.y;
    #pragma unroll
    for (int i = 0; i < 4; ++i)
        t[ty + 8 * i][tx] = in[base + (size_t)(r0 + ty + 8 * i) * C + c0 + tx];
    __syncthreads();
    #pragma unroll
    for (int i = 0; i < 4; ++i) {
        float v = t[tx][ty + 8 * i];
        bf16 h = __float2bfloat16(v);
        size_t o = base + (size_t)(c0 + ty + 8 * i) * R + r0 + tx;
        ohi[o] = h;
        olo[o] = __float2bfloat16(v - __bfloat162float(h));
    }
}

// Transpose fp32 [R,C] -> fp32 [C,R]  (per batch via blockIdx.z)
__global__ void transpose_f32(const float* __restrict__ in, float* __restrict__ out,
                              int R, int C) {
    __shared__ float t[32][33];
    size_t base = (size_t)blockIdx.z * R * C;
    int c0 = blockIdx.x * 32, r0 = blockIdx.y * 32;
    int tx = threadIdx.x, ty = threadIdx.y;
    #pragma unroll
    for (int i = 0; i < 4; ++i)
        t[ty + 8 * i][tx] = in[base + (size_t)(r0 + ty + 8 * i) * C + c0 + tx];
    __syncthreads();
    #pragma unroll
    for (int i = 0; i < 4; ++i)
        out[base + (size_t)(c0 + ty + 8 * i) * R + r0 + tx] = t[tx][ty + 8 * i];
}

// ---------------------------------------------------------------------------
// Launch
// ---------------------------------------------------------------------------
extern "C" void kernel_launch(void* const* d_in, const int* in_sizes, int n_in,
                              void* d_out, int out_size) {
    const float* x    = (const float*)d_in[0];
    const float* w0   = (const float*)d_in[1];
    const float* w1   = (const float*)d_in[2];
    const float* wout = (const float*)d_in[3];
    float* out = (float*)d_out;

    void *xThi, *xTlo, *w0hi, *w0lo, *w1hi, *w1lo, *wohi, *wolo, *hhi, *hlo, *oT;
    cudaGetSymbolAddress(&xThi, g_xThi);
    cudaGetSymbolAddress(&xTlo, g_xTlo);
    cudaGetSymbolAddress(&w0hi, g_w0hi);
    cudaGetSymbolAddress(&w0lo, g_w0lo);
    cudaGetSymbolAddress(&w1hi, g_w1hi);
    cudaGetSymbolAddress(&w1lo, g_w1lo);
    cudaGetSymbolAddress(&wohi, g_wohi);
    cudaGetSymbolAddress(&wolo, g_wolo);
    cudaGetSymbolAddress(&hhi,  g_hhi);
    cudaGetSymbolAddress(&hlo,  g_hlo);
    cudaGetSymbolAddress(&oT,   g_oT);

    cudaFuncSetAttribute(gemm1_fused, cudaFuncAttributeMaxDynamicSharedMemorySize, G1_SMEM);
    cudaFuncSetAttribute(gemm_mma,    cudaFuncAttributeMaxDynamicSharedMemorySize, SMEM_TOT);

    const int nW = F_ * D_;        // 67,108,864

    // 1) transpose+split x: [b][D][S] fp32 -> [b][S][D] bf16 hi/lo
    {
        dim3 blk(32, 8), grd(S_ / 32, D_ / 32, B_);
        transpose_split<<<grd, blk>>>(x, (bf16*)xThi, (bf16*)xTlo, D_, S_);
    }
    // 2) split weights (K-major already)
    split_kernel<<<nW / 4 / 256, 256>>>((const float4*)w0,   (ushort4*)w0hi, (ushort4*)w0lo, nW / 4);
    split_kernel<<<nW / 4 / 256, 256>>>((const float4*)w1,   (ushort4*)w1hi, (ushort4*)w1lo, nW / 4);
    split_kernel<<<nW / 4 / 256, 256>>>((const float4*)wout, (ushort4*)wohi, (ushort4*)wolo, nW / 4);

    // 3) fused layer 1: H^T[S,F] = gelu(X^T W0^T) * (X^T W1^T), bf16 hi/lo
    {
        dim3 grd(S_ / 128, F_ / 64, B_);      // (16, 256, 2)
        gemm1_fused<<<grd, 256, G1_SMEM>>>(
            (const bf16*)xThi, (const bf16*)xTlo,
            (const bf16*)w0hi, (const bf16*)w0lo,
            (const bf16*)w1hi, (const bf16*)w1lo,
            (bf16*)hhi, (bf16*)hlo);
    }

    // 4) layer 2: out^T[S,D] = H^T Wout^T
    {
        dim3 grd(S_ / BM, D_ / BN, B_);       // (16, 32, 2)
        gemm_mma<<<grd, 256, SMEM_TOT>>>(
            (const bf16*)hhi, (const bf16*)hlo,
            (const bf16*)wohi, (const bf16*)wolo,
            (float*)oT, D_, F_,
            (unsigned long long)S_ * F_, (unsigned long long)S_ * D_);
    }

    // 5) transpose out^T [b][S][D] -> out [b][D][S] fp32
    {
        dim3 blk(32, 8), grd(D_ / 32, S_ / 32, B_);
        transpose_f32<<<grd, blk>>>((const float*)oT, out, S_, D_);
    }
}

// round 12
// speedup vs baseline: 2.4286x; 1.0281x over previous
#include <cuda_runtime.h>
#include <cuda_bf16.h>
#include <stdint.h>

typedef __nv_bfloat16 bf16;

// Problem dims (fixed)
#define B_ 2
#define D_ 4096
#define S_ 2048
#define F_ 16384

// ---------------------------------------------------------------------------
// Scratch (device globals; allocation-free per harness rules)
// ---------------------------------------------------------------------------
__device__ bf16  g_xThi[(size_t)B_ * S_ * D_];   // x^T per batch [S, D]
__device__ bf16  g_xTlo[(size_t)B_ * S_ * D_];
__device__ bf16  g_w0hi[(size_t)F_ * D_];
__device__ bf16  g_w0lo[(size_t)F_ * D_];
__device__ bf16  g_w1hi[(size_t)F_ * D_];
__device__ bf16  g_w1lo[(size_t)F_ * D_];
__device__ bf16  g_wohi[(size_t)D_ * F_];
__device__ bf16  g_wolo[(size_t)D_ * F_];
__device__ bf16  g_hhi[(size_t)B_ * S_ * F_];    // H^T  [S, F]
__device__ bf16  g_hlo[(size_t)B_ * S_ * F_];

// ---------------------------------------------------------------------------
// PTX helpers (sm_80-era only; NO tcgen05 — ptxas targets plain sm_103)
// ---------------------------------------------------------------------------
__device__ __forceinline__ void cp16(uint32_t s, const void* g) {
    asm volatile("cp.async.cg.shared.global [%0], [%1], 16;\n" :: "r"(s), "l"(g));
}

__device__ __forceinline__ void ldsm_x4(uint32_t addr, uint32_t* r) {
    asm volatile(
        "ldmatrix.sync.aligned.m8n8.x4.shared.b16 {%0,%1,%2,%3}, [%4];\n"
        : "=r"(r[0]), "=r"(r[1]), "=r"(r[2]), "=r"(r[3]) : "r"(addr));
}

__device__ __forceinline__ void mma_bf16(float* c, const uint32_t* a,
                                         uint32_t b0, uint32_t b1) {
    asm volatile(
        "mma.sync.aligned.m16n8k16.row.col.f32.bf16.bf16.f32 "
        "{%0,%1,%2,%3}, {%4,%5,%6,%7}, {%8,%9}, {%0,%1,%2,%3};\n"
        : "+f"(c[0]), "+f"(c[1]), "+f"(c[2]), "+f"(c[3])
        : "r"(a[0]), "r"(a[1]), "r"(a[2]), "r"(a[3]), "r"(b0), "r"(b1));
}

__device__ __forceinline__ float gelu_exact(float v) {
    return 0.5f * v * (1.0f + erff(v * 0.70710678118654752440f));
}

#define SWZ(x) ((x) ^ (((x) >> 3) & 0x70))

// ===========================================================================
// GEMM1 fused: CTA tile 256(S) x 64(F) PER PRODUCT; warps 0-3 compute
// gate = (xT)(w0^T), warps 4-7 compute up = (xT)(w1^T); warp tile 64x64.
// bf16x3 products, fp32 accum. Epilogue: h = gelu(gate)*up -> bf16 hi/lo.
// 2-stage cp.async pipeline, BK=64, SW128 swizzle.
// Stage layout: Ahi 32K | Alo 32K | W0h 8K | W0l 8K | W1h 8K | W1l 8K = 96K
// ===========================================================================
constexpr int BK = 64;
constexpr int G1_STAGE = 98304;
constexpr int G1_SMEM  = 2 * G1_STAGE;           // 196608

__device__ __forceinline__ void g1_load_stage(
    uint32_t st, const bf16* __restrict__ Ah, const bf16* __restrict__ Al,
    const bf16* __restrict__ W0h, const bf16* __restrict__ W0l,
    const bf16* __restrict__ W1h, const bf16* __restrict__ W1l,
    size_t m0, size_t n0, int k0, int tid) {
    const int K = D_;
    // A: 256 rows x 128B, hi+lo
    #pragma unroll
    for (int i = 0; i < 8; ++i) {
        int cc = i * 256 + tid;           // 0..2047
        int r = cc >> 3, cb = (cc & 7) * 16;
        size_t gbyte = (((m0 + r) * (size_t)K + k0) << 1) + cb;
        uint32_t s = SWZ((uint32_t)(r * 128 + cb));
        cp16(st + s,         (const char*)Ah + gbyte);
        cp16(st + 32768 + s, (const char*)Al + gbyte);
    }
    // B: 4 subtiles (w0h,w0l,w1h,w1l), each 64 rows x 128B
    #pragma unroll
    for (int i = 0; i < 8; ++i) {
        int sub = i >> 1;                 // compile-time
        int cc  = (i & 1) * 256 + tid;    // 0..511
        int r = cc >> 3, cb = (cc & 7) * 16;
        size_t gbyte = (((n0 + r) * (size_t)K + k0) << 1) + cb;
        uint32_t s = SWZ((uint32_t)(r * 128 + cb));
        const bf16* p = (sub == 0) ? W0h : (sub == 1) ? W0l : (sub == 2) ? W1h : W1l;
        cp16(st + 65536 + sub * 8192 + s, (const char*)p + gbyte);
    }
}

__global__ void __launch_bounds__(256, 1) gemm1_fused(
    const bf16* __restrict__ Ah, const bf16* __restrict__ Al,
    const bf16* __restrict__ W0h, const bf16* __restrict__ W0l,
    const bf16* __restrict__ W1h, const bf16* __restrict__ W1l,
    bf16* __restrict__ Hhi, bf16* __restrict__ Hlo) {
    extern __shared__ char smem[];
    uint32_t sb = (uint32_t)__cvta_generic_to_shared(smem);
    int tid = threadIdx.x, wid = tid >> 5, lane = tid & 31;
    int grp = wid >> 2;        // 0 = gate(w0), 1 = up(w1)
    int wg  = wid & 3;         // 4 warps along M, 64 rows each

    int b = blockIdx.z;
    const bf16* xh = Ah + (size_t)b * S_ * D_;
    const bf16* xl = Al + (size_t)b * S_ * D_;
    bf16* Oh = Hhi + (size_t)b * S_ * F_;
    bf16* Ol = Hlo + (size_t)b * S_ * F_;
    size_t m0 = (size_t)blockIdx.x * 256;
    size_t n0 = (size_t)blockIdx.y * 64;
    const int KT = D_ / BK;    // 64

    float c[4][8][4];
    #pragma unroll
    for (int mi = 0; mi < 4; ++mi)
        #pragma unroll
        for (int ni = 0; ni < 8; ++ni)
            #pragma unroll
            for (int r = 0; r < 4; ++r) c[mi][ni][r] = 0.0f;

    g1_load_stage(sb,            xh, xl, W0h, W0l, W1h, W1l, m0, n0, 0,  tid);
    asm volatile("cp.async.commit_group;\n" ::: "memory");
    g1_load_stage(sb + G1_STAGE, xh, xl, W0h, W0l, W1h, W1l, m0, n0, BK, tid);
    asm volatile("cp.async.commit_group;\n" ::: "memory");

    int aRow = wg * 64 + (lane & 15);
    int aCol = (lane >> 4) * 16;
    int bRow = (lane & 7) + ((lane >> 4) << 3);
    int bCol = ((lane >> 3) & 1) * 16;
    uint32_t bBase = 65536 + grp * 16384;   // this group's B (hi @+0, lo @+8192)

    for (int kt = 0; kt < KT; ++kt) {
        if (kt + 1 < KT) asm volatile("cp.async.wait_group 1;\n" ::: "memory");
        else             asm volatile("cp.async.wait_group 0;\n" ::: "memory");
        __syncthreads();
        uint32_t st = sb + (kt & 1) * G1_STAGE;

        #pragma unroll
        for (int ks = 0; ks < 4; ++ks) {
            uint32_t ah[4][4], al[4][4], bh[4][4], bl[4][4];
            #pragma unroll
            for (int mi = 0; mi < 4; ++mi) {
                uint32_t off = SWZ((uint32_t)((aRow + mi * 16) * 128 + ks * 32 + aCol));
                ldsm_x4(st + off,         ah[mi]);
                ldsm_x4(st + 32768 + off, al[mi]);
            }
            #pragma unroll
            for (int nj = 0; nj < 4; ++nj) {
                uint32_t off = SWZ((uint32_t)((bRow + nj * 16) * 128 + ks * 32 + bCol));
                ldsm_x4(st + bBase + off,        bh[nj]);
                ldsm_x4(st + bBase + 8192 + off, bl[nj]);
            }
            // term 1: Ahi * Bhi  (independent accumulators back-to-back)
            #pragma unroll
            for (int mi = 0; mi < 4; ++mi)
                #pragma unroll
                for (int ni = 0; ni < 8; ++ni) {
                    int nj = ni >> 1, pr = (ni & 1) * 2;
                    mma_bf16(c[mi][ni], ah[mi], bh[nj][pr], bh[nj][pr + 1]);
                }
            // term 2: Ahi * Blo
            #pragma unroll
            for (int mi = 0; mi < 4; ++mi)
                #pragma unroll
                for (int ni = 0; ni < 8; ++ni) {
                    int nj = ni >> 1, pr = (ni & 1) * 2;
                    mma_bf16(c[mi][ni], ah[mi], bl[nj][pr], bl[nj][pr + 1]);
                }
            // term 3: Alo * Bhi
            #pragma unroll
            for (int mi = 0; mi < 4; ++mi)
                #pragma unroll
                for (int ni = 0; ni < 8; ++ni) {
                    int nj = ni >> 1, pr = (ni & 1) * 2;
                    mma_bf16(c[mi][ni], al[mi], bh[nj][pr], bh[nj][pr + 1]);
                }
        }
        __syncthreads();   // stage fully consumed; safe to refill below
        if (kt + 2 < KT) {
            g1_load_stage(st, xh, xl, W0h, W0l, W1h, W1l, m0, n0, (kt + 2) * BK, tid);
            asm volatile("cp.async.commit_group;\n" ::: "memory");
        }
    }

    // ---- Fused epilogue: h = gelu(gate) * up, split bf16 hi/lo ----
    __syncthreads();
    float* gsm = (float*)smem;               // 4 warps x 4096 floats = 64KB
    int slotBase = wg * 4096 + lane;         // lane-major: conflict-free
    if (grp == 0) {
        #pragma unroll
        for (int mi = 0; mi < 4; ++mi)
            #pragma unroll
            for (int ni = 0; ni < 8; ++ni)
                #pragma unroll
                for (int r = 0; r < 4; ++r)
                    gsm[slotBase + (mi * 32 + ni * 4 + r) * 32] = c[mi][ni][r];
    }
    __syncthreads();
    if (grp == 1) {
        #pragma unroll
        for (int mi = 0; mi < 4; ++mi) {
            #pragma unroll
            for (int ni = 0; ni < 8; ++ni) {
                float h[4];
                #pragma unroll
                for (int r = 0; r < 4; ++r) {
                    float gate = gsm[slotBase + (mi * 32 + ni * 4 + r) * 32];
                    h[r] = gelu_exact(gate) * c[mi][ni][r];
                }
                size_t row = m0 + wg * 64 + mi * 16 + (lane >> 2);
                size_t col = n0 + ni * 8 + (lane & 3) * 2;
                #pragma unroll
                for (int half = 0; half < 2; ++half) {
                    float v0 = h[half * 2], v1 = h[half * 2 + 1];
                    bf16 h0 = __float2bfloat16(v0), h1 = __float2bfloat16(v1);
                    __nv_bfloat162 hi2 = { h0, h1 };
                    __nv_bfloat162 lo2 = { __float2bfloat16(v0 - __bfloat162float(h0)),
                                           __float2bfloat16(v1 - __bfloat162float(h1)) };
                    size_t o = (row + half * 8) * (size_t)F_ + col;
                    *(__nv_bfloat162*)(Oh + o) = hi2;
                    *(__nv_bfloat162*)(Ol + o) = lo2;
                }
            }
        }
    }
}

// ===========================================================================
// GEMM2: out^T-free — computes C fp32 = (Ahi+Alo)[S,K] @ (Bhi+Blo)[D,K]^T and
// writes out[b][d][s] DIRECTLY (transposed scatter epilogue).
// CTA 128x128, BK=64, 3 stages, one barrier per stage, warp tile 64x32.
// ===========================================================================
constexpr int BM = 128, BN = 128;
constexpr int SUB   = BM * 128;             // 16384 B per sub-tile
constexpr int STAGE = 4 * SUB;              // 65536 B
constexpr int NSTG  = 3;
constexpr int SMEM_TOT = NSTG * STAGE;      // 196608 B

__device__ __forceinline__ void load_stage(
    uint32_t st, const bf16* __restrict__ Ah, const bf16* __restrict__ Al,
    const bf16* __restrict__ Bh, const bf16* __restrict__ Bl,
    size_t m0, size_t n0, int k0, int K, int tid) {
    #pragma unroll
    for (int i = 0; i < 4; ++i) {
        int c = tid + i * 256;
        int r = c >> 3, cb = (c & 7) * 16;
        size_t gbyte = (((m0 + r) * (size_t)K + k0) << 1) + cb;
        uint32_t s = SWZ((uint32_t)(r * 128 + cb));
        cp16(st + s,       (const char*)Ah + gbyte);
        cp16(st + SUB + s, (const char*)Al + gbyte);
    }
    #pragma unroll
    for (int i = 0; i < 4; ++i) {
        int c = tid + i * 256;
        int r = c >> 3, cb = (c & 7) * 16;
        size_t gbyte = (((n0 + r) * (size_t)K + k0) << 1) + cb;
        uint32_t s = SWZ((uint32_t)(r * 128 + cb));
        cp16(st + 2 * SUB + s, (const char*)Bh + gbyte);
        cp16(st + 3 * SUB + s, (const char*)Bl + gbyte);
    }
}

__global__ void __launch_bounds__(256, 1) gemm2_mma(
    const bf16* __restrict__ gAh, const bf16* __restrict__ gAl,
    const bf16* __restrict__ Bh, const bf16* __restrict__ Bl,
    float* __restrict__ gOut) {
    extern __shared__ char smem[];
    uint32_t sb = (uint32_t)__cvta_generic_to_shared(smem);
    int tid = threadIdx.x, wid = tid >> 5, lane = tid & 31;
    int wm = wid >> 2;        // 2 warps along M(S), 64 rows each
    int wn = wid & 3;         // 4 warps along N(D), 32 cols each

    int b = blockIdx.z;
    const bf16* Ah = gAh + (size_t)b * S_ * F_;
    const bf16* Al = gAl + (size_t)b * S_ * F_;
    float* Out = gOut + (size_t)b * D_ * S_;
    size_t m0 = (size_t)blockIdx.x * BM;
    size_t n0 = (size_t)blockIdx.y * BN;
    const int K = F_;
    const int KT = K / BK;

    float c[4][4][4];
    #pragma unroll
    for (int mi = 0; mi < 4; ++mi)
        #pragma unroll
        for (int ni = 0; ni < 4; ++ni)
            #pragma unroll
            for (int r = 0; r < 4; ++r) c[mi][ni][r] = 0.0f;

    load_stage(sb,         Ah, Al, Bh, Bl, m0, n0, 0,  K, tid);
    asm volatile("cp.async.commit_group;\n" ::: "memory");
    load_stage(sb + STAGE, Ah, Al, Bh, Bl, m0, n0, BK, K, tid);
    asm volatile("cp.async.commit_group;\n" ::: "memory");

    int aRow = wm * 64 + (lane & 15);
    int aCol = (lane >> 4) * 16;
    int bRow = wn * 32 + (lane & 7) + ((lane >> 4) << 3);
    int bCol = ((lane >> 3) & 1) * 16;

    for (int kt = 0; kt < KT; ++kt) {
        if (kt + 1 < KT) asm volatile("cp.async.wait_group 1;\n" ::: "memory");
        else             asm volatile("cp.async.wait_group 0;\n" ::: "memory");
        __syncthreads();   // sole barrier per stage

        uint32_t st = sb + (kt % NSTG) * STAGE;
        if (kt + 2 < KT) {
            load_stage(sb + ((kt + 2) % NSTG) * STAGE, Ah, Al, Bh, Bl,
                       m0, n0, (kt + 2) * BK, K, tid);
            asm volatile("cp.async.commit_group;\n" ::: "memory");
        }

        #pragma unroll
        for (int ks = 0; ks < 4; ++ks) {
            uint32_t ah[4][4], al[4][4], bh[2][4], bl[2][4];
            #pragma unroll
            for (int mi = 0; mi < 4; ++mi) {
                uint32_t off = SWZ((uint32_t)((aRow + mi * 16) * 128 + ks * 32 + aCol));
                ldsm_x4(st + off,       ah[mi]);
                ldsm_x4(st + SUB + off, al[mi]);
            }
            #pragma unroll
            for (int nj = 0; nj < 2; ++nj) {
                uint32_t off = SWZ((uint32_t)((bRow + nj * 16) * 128 + ks * 32 + bCol));
                ldsm_x4(st + 2 * SUB + off, bh[nj]);
                ldsm_x4(st + 3 * SUB + off, bl[nj]);
            }
            #pragma unroll
            for (int mi = 0; mi < 4; ++mi)
                #pragma unroll
                for (int ni = 0; ni < 4; ++ni) {
                    int nj = ni >> 1, pr = (ni & 1) * 2;
                    mma_bf16(c[mi][ni], ah[mi], bh[nj][pr], bh[nj][pr + 1]);
                }
            #pragma unroll
            for (int mi = 0; mi < 4; ++mi)
                #pragma unroll
                for (int ni = 0; ni < 4; ++ni) {
                    int nj = ni >> 1, pr = (ni & 1) * 2;
                    mma_bf16(c[mi][ni], ah[mi], bl[nj][pr], bl[nj][pr + 1]);
                }
            #pragma unroll
            for (int mi = 0; mi < 4; ++mi)
                #pragma unroll
                for (int ni = 0; ni < 4; ++ni) {
                    int nj = ni >> 1, pr = (ni & 1) * 2;
                    mma_bf16(c[mi][ni], al[mi], bh[nj][pr], bh[nj][pr + 1]);
                }
        }
    }

    // Transposed scatter epilogue: out[b][d][s] = C[s][d]
    #pragma unroll
    for (int mi = 0; mi < 4; ++mi) {
        #pragma unroll
        for (int ni = 0; ni < 4; ++ni) {
            size_t row = m0 + wm * 64 + mi * 16 + (lane >> 2);   // s
            size_t col = n0 + wn * 32 + ni * 8 + (lane & 3) * 2; // d
            float* o = Out + col * (size_t)S_ + row;
            o[0]           = c[mi][ni][0];
            o[(size_t)S_]  = c[mi][ni][1];
            o[8]           = c[mi][ni][2];
            o[(size_t)S_ + 8] = c[mi][ni][3];
        }
    }
}

// ---------------------------------------------------------------------------
// Elementwise kernels
// ---------------------------------------------------------------------------
__global__ void split_kernel(const float4* __restrict__ in,
                             ushort4* __restrict__ hi,
                             ushort4* __restrict__ lo, int n4) {
    int i = blockIdx.x * blockDim.x + threadIdx.x;
    if (i >= n4) return;
    float4 v = in[i];
    __nv_bfloat16 h0 = __float2bfloat16(v.x), h1 = __float2bfloat16(v.y);
    __nv_bfloat16 h2 = __float2bfloat16(v.z), h3 = __float2bfloat16(v.w);
    ushort4 H = { __bfloat16_as_ushort(h0), __bfloat16_as_ushort(h1),
                  __bfloat16_as_ushort(h2), __bfloat16_as_ushort(h3) };
    hi[i] = H;
    ushort4 L = { __bfloat16_as_ushort(__float2bfloat16(v.x - __bfloat162float(h0))),
                  __bfloat16_as_ushort(__float2bfloat16(v.y - __bfloat162float(h1))),
                  __bfloat16_as_ushort(__float2bfloat16(v.z - __bfloat162float(h2))),
                  __bfloat16_as_ushort(__float2bfloat16(v.w - __bfloat162float(h3))) };
    lo[i] = L;
}

// Transpose fp32 [R,C] -> bf16 hi/lo [C,R]  (per batch via blockIdx.z)
__global__ void transpose_split(const float* __restrict__ in,
                                bf16* __restrict__ ohi, bf16* __restrict__ olo,
                                int R, int C) {
    __shared__ float t[32][33];
    size_t base = (size_t)blockIdx.z * R * C;
    int c0 = blockIdx.x * 32, r0 = blockIdx.y * 32;
    int tx = threadIdx.x, ty = threadIdx.y;
    #pragma unroll
    for (int i = 0; i < 4; ++i)
        t[ty + 8 * i][tx] = in[base + (size_t)(r0 + ty + 8 * i) * C + c0 + tx];
    __syncthreads();
    #pragma unroll
    for (int i = 0; i < 4; ++i) {
        float v = t[tx][ty + 8 * i];
        bf16 h = __float2bfloat16(v);
        size_t o = base + (size_t)(c0 + ty + 8 * i) * R + r0 + tx;
        ohi[o] = h;
        olo[o] = __float2bfloat16(v - __bfloat162float(h));
    }
}

// ---------------------------------------------------------------------------
// Launch
// ---------------------------------------------------------------------------
extern "C" void kernel_launch(void* const* d_in, const int* in_sizes, int n_in,
                              void* d_out, int out_size) {
    const float* x    = (const float*)d_in[0];
    const float* w0   = (const float*)d_in[1];
    const float* w1   = (const float*)d_in[2];
    const float* wout = (const float*)d_in[3];
    float* out = (float*)d_out;

    void *xThi, *xTlo, *w0hi, *w0lo, *w1hi, *w1lo, *wohi, *wolo, *hhi, *hlo;
    cudaGetSymbolAddress(&xThi, g_xThi);
    cudaGetSymbolAddress(&xTlo, g_xTlo);
    cudaGetSymbolAddress(&w0hi, g_w0hi);
    cudaGetSymbolAddress(&w0lo, g_w0lo);
    cudaGetSymbolAddress(&w1hi, g_w1hi);
    cudaGetSymbolAddress(&w1lo, g_w1lo);
    cudaGetSymbolAddress(&wohi, g_wohi);
    cudaGetSymbolAddress(&wolo, g_wolo);
    cudaGetSymbolAddress(&hhi,  g_hhi);
    cudaGetSymbolAddress(&hlo,  g_hlo);

    cudaFuncSetAttribute(gemm1_fused, cudaFuncAttributeMaxDynamicSharedMemorySize, G1_SMEM);
    cudaFuncSetAttribute(gemm2_mma,   cudaFuncAttributeMaxDynamicSharedMemorySize, SMEM_TOT);

    const int nW = F_ * D_;        // 67,108,864

    // 1) transpose+split x: [b][D][S] fp32 -> [b][S][D] bf16 hi/lo
    {
        dim3 blk(32, 8), grd(S_ / 32, D_ / 32, B_);
        transpose_split<<<grd, blk>>>(x, (bf16*)xThi, (bf16*)xTlo, D_, S_);
    }
    // 2) split weights (K-major already)
    split_kernel<<<nW / 4 / 256, 256>>>((const float4*)w0,   (ushort4*)w0hi, (ushort4*)w0lo, nW / 4);
    split_kernel<<<nW / 4 / 256, 256>>>((const float4*)w1,   (ushort4*)w1hi, (ushort4*)w1lo, nW / 4);
    split_kernel<<<nW / 4 / 256, 256>>>((const float4*)wout, (ushort4*)wohi, (ushort4*)wolo, nW / 4);

    // 3) fused layer 1: H^T[S,F] = gelu(X^T W0^T) * (X^T W1^T), bf16 hi/lo
    {
        dim3 grd(S_ / 256, F_ / 64, B_);      // (8, 256, 2)
        gemm1_fused<<<grd, 256, G1_SMEM>>>(
            (const bf16*)xThi, (const bf16*)xTlo,
            (const bf16*)w0hi, (const bf16*)w0lo,
            (const bf16*)w1hi, (const bf16*)w1lo,
            (bf16*)hhi, (bf16*)hlo);
    }

    // 4) layer 2 + transposed epilogue: out[b][d][s] = (H^T Wout^T)[s][d]
    {
        dim3 grd(S_ / BM, D_ / BN, B_);       // (16, 32, 2)
        gemm2_mma<<<grd, 256, SMEM_TOT>>>(
            (const bf16*)hhi, (const bf16*)hlo,
            (const bf16*)wohi, (const bf16*)wolo,
            out);
    }
}